// round 4
// baseline (speedup 1.0000x reference)
#include <cuda_runtime.h>
#include <math.h>

#define TEMP 0.0005f

// Problem shapes (fixed): B=32, C_MEL=80, C_TXT=512, C_ATT=80, T1=1600, T2=400

// ---------------- scratch ----------------
#define OFF_KEYS_ADJ 0LL
#define OFF_K1       6553600LL
#define OFF_K        19660800LL
#define OFF_QADJ     20684800LL
#define OFF_Q1       24780800LL
#define OFF_Q2       32972800LL
#define OFF_Q3       37068800LL
#define SCRATCH_TOTAL 41164800LL

__device__ float g_scratch[SCRATCH_TOTAL];

// mask storage kind: 0 = int32 (0/1), 1 = float32 (0.0/1.0), 2 = packed bytes
__device__ unsigned int g_mask_kind;

// Scan the first 3200 32-bit words (safe in-bounds for byte/int/float layouts:
// byte layout is exactly 3200 words; int/float layouts are 12800 words).
// Packed-byte layout produces words with byte-values in {0,1} -> words like
// 0x00010100 that are neither 0/1 nor 0x3F800000. int32 layout words are
// exactly 0 or 1. float layout words are 0 or 0x3F800000.
__global__ void detect_mask_kind(const unsigned int* __restrict__ mw)
{
    __shared__ unsigned int kinds;
    if (threadIdx.x == 0) kinds = 0u;
    __syncthreads();
    unsigned int local = 0u;
    for (int i = threadIdx.x; i < 3200; i += blockDim.x) {
        unsigned int v = mw[i];
        if (v == 0u) continue;
        else if (v == 1u) local |= 1u;
        else if (v == 0x3F800000u) local |= 2u;
        else local |= 4u;
    }
    atomicOr(&kinds, local);
    __syncthreads();
    if (threadIdx.x == 0) {
        unsigned int k = kinds;
        unsigned int kind;
        if (k & 4u) kind = 2u;        // impossible for int/float -> packed bytes
        else if (k & 2u) kind = 1u;   // float 1.0 pattern seen
        else kind = 0u;               // pure 0/1 words -> int32
        g_mask_kind = kind;
    }
}

// ---------------- speaker bias add ----------------
__global__ __launch_bounds__(256) void add_spk_bias(
    const float* __restrict__ x, const float* __restrict__ spk,
    const float* __restrict__ Wm, const float* __restrict__ bb,
    float* __restrict__ out, int C, int T)
{
    __shared__ float sb[512];
    int b = blockIdx.x;
    int tid = threadIdx.x;
    const float* sp = spk + b * 512;
    for (int c = tid; c < C; c += 256) {
        const float* wrow = Wm + c * 512;
        float s = bb[c];
        #pragma unroll 4
        for (int j = 0; j < 512; j++) s += sp[j] * wrow[j];
        sb[c] = s;
    }
    __syncthreads();
    int n = C * T;
    const float* xb = x + (long long)b * n;
    float* ob = out + (long long)b * n;
    for (int i = tid; i < n; i += 256) ob[i] = xb[i] + sb[i / T];
}

// ---------------- conv1d as tiled GEMM ----------------
// out[b,co,t] = act( bias[co] + sum_{ci,tap} W[co,ci,tap] * in[b,ci,t+tap-PAD] )
// 128 co x 128 t per block, 256 threads, 8x8 per thread, interleaved t mapping.
template<int TAPS, bool RELU>
__global__ __launch_bounds__(256, 2) void conv_kernel(
    const float* __restrict__ in, const float* __restrict__ W,
    const float* __restrict__ bias, float* __restrict__ out,
    int Cin, int Cout, int T)
{
    constexpr int PAD = (TAPS - 1) / 2;
    constexpr int KC = 16;
    constexpr int TW = 128 + TAPS - 1;
    __shared__ float Ws[KC][TAPS][128];
    __shared__ float Is[KC][TW];

    int tid = threadIdx.x;
    int tx = tid & 15;
    int ty = tid >> 4;
    int t0 = blockIdx.x * 128;
    int co0 = blockIdx.y * 128;
    int b = blockIdx.z;

    float acc[8][8];
    #pragma unroll
    for (int i = 0; i < 8; i++)
        #pragma unroll
        for (int j = 0; j < 8; j++) acc[i][j] = 0.f;

    const float* inb = in + (long long)b * Cin * T;

    for (int ci0 = 0; ci0 < Cin; ci0 += KC) {
        for (int idx = tid; idx < 128 * KC * TAPS; idx += 256) {
            int co = idx / (KC * TAPS);
            int r = idx - co * (KC * TAPS);
            int ci = r / TAPS;
            int tap = r - ci * TAPS;
            float v = 0.f;
            if (co0 + co < Cout)
                v = W[((long long)(co0 + co) * Cin + (ci0 + ci)) * TAPS + tap];
            Ws[ci][tap][co] = v;
        }
        for (int idx = tid; idx < KC * TW; idx += 256) {
            int ci = idx / TW;
            int j = idx - ci * TW;
            int t = t0 + j - PAD;
            float v = 0.f;
            if (t >= 0 && t < T) v = inb[(ci0 + ci) * T + t];
            Is[ci][j] = v;
        }
        __syncthreads();

        #pragma unroll 2
        for (int ci = 0; ci < KC; ci++) {
            #pragma unroll
            for (int tap = 0; tap < TAPS; tap++) {
                float wv[8], xv[8];
                #pragma unroll
                for (int i = 0; i < 8; i++) wv[i] = Ws[ci][tap][ty * 8 + i];
                #pragma unroll
                for (int j = 0; j < 8; j++) xv[j] = Is[ci][tx + 16 * j + tap];
                #pragma unroll
                for (int i = 0; i < 8; i++)
                    #pragma unroll
                    for (int j = 0; j < 8; j++)
                        acc[i][j] += wv[i] * xv[j];
            }
        }
        __syncthreads();
    }

    #pragma unroll
    for (int i = 0; i < 8; i++) {
        int co = co0 + ty * 8 + i;
        if (co < Cout) {
            float bv = bias[co];
            float* ob = out + ((long long)b * Cout + co) * T;
            #pragma unroll
            for (int j = 0; j < 8; j++) {
                int t = t0 + tx + 16 * j;
                if (t < T) {
                    float v = acc[i][j] + bv;
                    if (RELU) v = fmaxf(v, 0.f);
                    ob[t] = v;
                }
            }
        }
    }
}

// ---------------- fused attention ----------------
__device__ __forceinline__ float warpMax(float v) {
    #pragma unroll
    for (int o = 16; o > 0; o >>= 1) v = fmaxf(v, __shfl_xor_sync(0xffffffffu, v, o));
    return v;
}
__device__ __forceinline__ float warpSum(float v) {
    #pragma unroll
    for (int o = 16; o > 0; o >>= 1) v += __shfl_xor_sync(0xffffffffu, v, o);
    return v;
}

// block: (t1 tile of 32, b). 8 warps; each warp owns 4 t1 rows; lanes split s.
__global__ __launch_bounds__(256) void attn_kernel(
    const float* __restrict__ q, const float* __restrict__ k,
    const float* __restrict__ prior, const void* __restrict__ maskp,
    float* __restrict__ attn_out, float* __restrict__ logprob_out)
{
    extern __shared__ float smem[];
    float* ksh  = smem;               // 80*400
    float* k2sh = smem + 80 * 400;    // 400
    float* qsh  = k2sh + 400;         // 80*32
    __shared__ unsigned char msh[400];

    int b = blockIdx.y;
    int t1_0 = blockIdx.x * 32;
    int tid = threadIdx.x;
    int w = tid >> 5;
    int lane = tid & 31;

    // decode mask row for this batch according to detected storage kind
    {
        unsigned int kind = g_mask_kind;
        if (kind == 0u) {
            const int* mi = (const int*)maskp;
            for (int s = tid; s < 400; s += 256) msh[s] = (mi[b * 400 + s] != 0);
        } else if (kind == 1u) {
            const float* mf = (const float*)maskp;
            for (int s = tid; s < 400; s += 256) msh[s] = (mf[b * 400 + s] != 0.f);
        } else {
            const unsigned char* mu = (const unsigned char*)maskp;
            for (int s = tid; s < 400; s += 256) msh[s] = (mu[b * 400 + s] != 0);
        }
    }

    const float* kb = k + (long long)b * 80 * 400;
    for (int i = tid; i < 80 * 400; i += 256) ksh[i] = kb[i];
    const float* qb = q + (long long)b * 80 * 1600;
    for (int i = tid; i < 80 * 32; i += 256) {
        int c = i >> 5; int t = i & 31;
        qsh[i] = qb[c * 1600 + t1_0 + t];
    }
    __syncthreads();
    for (int s = tid; s < 400; s += 256) {
        float a = 0.f;
        #pragma unroll 4
        for (int c = 0; c < 80; c++) { float v = ksh[c * 400 + s]; a += v * v; }
        k2sh[s] = a;
    }
    __syncthreads();

    float acc[4][13];
    #pragma unroll
    for (int jj = 0; jj < 4; jj++)
        #pragma unroll
        for (int i = 0; i < 13; i++) acc[jj][i] = 0.f;
    float q2v[4] = {0.f, 0.f, 0.f, 0.f};

    #pragma unroll 2
    for (int c = 0; c < 80; c++) {
        float kv[13];
        #pragma unroll
        for (int i = 0; i < 13; i++) {
            int s = i * 32 + lane;
            kv[i] = (s < 400) ? ksh[c * 400 + s] : 0.f;
        }
        float qv[4];
        #pragma unroll
        for (int jj = 0; jj < 4; jj++) qv[jj] = qsh[c * 32 + w * 4 + jj];
        #pragma unroll
        for (int jj = 0; jj < 4; jj++) {
            q2v[jj] += qv[jj] * qv[jj];
            #pragma unroll
            for (int i = 0; i < 13; i++)
                acc[jj][i] += qv[jj] * kv[i];
        }
    }

    #pragma unroll 1
    for (int jj = 0; jj < 4; jj++) {
        int t1 = t1_0 + w * 4 + jj;
        float sc[13];
        float m = -INFINITY;
        #pragma unroll
        for (int i = 0; i < 13; i++) {
            int s = i * 32 + lane;
            sc[i] = (s < 400) ? (-TEMP * (q2v[jj] + k2sh[s] - 2.f * acc[jj][i]))
                              : -INFINITY;
            m = fmaxf(m, sc[i]);
        }
        m = warpMax(m);
        float sum = 0.f;
        #pragma unroll
        for (int i = 0; i < 13; i++) sum += expf(sc[i] - m);
        sum = warpSum(sum);
        float lse = m + logf(sum);

        long long base = ((long long)b * 1600 + t1) * 400;
        float xm[13];
        float m2 = -INFINITY;
        #pragma unroll
        for (int i = 0; i < 13; i++) {
            int s = i * 32 + lane;
            if (s < 400) {
                float lp = sc[i] - lse + logf(prior[base + s] + 1e-8f);
                logprob_out[base + s] = lp;
                bool mv = msh[s] != 0;
                xm[i] = mv ? -INFINITY : lp;
            } else xm[i] = -INFINITY;
            m2 = fmaxf(m2, xm[i]);
        }
        m2 = warpMax(m2);
        float s2 = 0.f;
        #pragma unroll
        for (int i = 0; i < 13; i++) {
            xm[i] = (xm[i] == -INFINITY) ? 0.f : expf(xm[i] - m2);
            s2 += xm[i];
        }
        s2 = warpSum(s2);
        float inv = 1.f / s2;
        #pragma unroll
        for (int i = 0; i < 13; i++) {
            int s = i * 32 + lane;
            if (s < 400) attn_out[base + s] = xm[i] * inv;
        }
    }
}

// ---------------- launch ----------------
extern "C" void kernel_launch(void* const* d_in, const int* in_sizes, int n_in,
                              void* d_out, int out_size)
{
    const float* queries = (const float*)d_in[0];
    const float* keys    = (const float*)d_in[1];
    const void*  mask    = (const void*)d_in[2];
    const float* prior   = (const float*)d_in[3];
    const float* spk     = (const float*)d_in[4];
    const float* Wk1 = (const float*)d_in[5];
    const float* bk1 = (const float*)d_in[6];
    const float* Wk2 = (const float*)d_in[7];
    const float* bk2 = (const float*)d_in[8];
    const float* Wq1 = (const float*)d_in[9];
    const float* bq1 = (const float*)d_in[10];
    const float* Wq2 = (const float*)d_in[11];
    const float* bq2 = (const float*)d_in[12];
    const float* Wq3 = (const float*)d_in[13];
    const float* bq3 = (const float*)d_in[14];
    const float* Wks = (const float*)d_in[15];
    const float* bks = (const float*)d_in[16];
    const float* Wqs = (const float*)d_in[17];
    const float* bqs = (const float*)d_in[18];

    float* out = (float*)d_out;
    float* attn_out = out;
    float* logprob_out = out + (long long)32 * 1600 * 400;

    float* sc = nullptr;
    cudaGetSymbolAddress((void**)&sc, g_scratch);
    float* keys_adj = sc + OFF_KEYS_ADJ;
    float* k1buf    = sc + OFF_K1;
    float* kbuf     = sc + OFF_K;
    float* q_adj    = sc + OFF_QADJ;
    float* q1buf    = sc + OFF_Q1;
    float* q2buf    = sc + OFF_Q2;
    float* q3buf    = sc + OFF_Q3;

    // detect mask storage layout (bool may arrive as int32/float32/bytes)
    detect_mask_kind<<<1, 256>>>((const unsigned int*)mask);

    // speaker-conditioned bias adds
    add_spk_bias<<<32, 256>>>(keys, spk, Wks, bks, keys_adj, 512, 400);
    add_spk_bias<<<32, 256>>>(queries, spk, Wqs, bqs, q_adj, 80, 1600);

    // K path: conv(512->1024, k3) + relu ; conv(1024->80, k1)
    conv_kernel<3, true ><<<dim3(4, 8, 32), 256>>>(keys_adj, Wk1, bk1, k1buf, 512, 1024, 400);
    conv_kernel<1, false><<<dim3(4, 1, 32), 256>>>(k1buf, Wk2, bk2, kbuf, 1024, 80, 400);

    // Q path: conv(80->160, k3)+relu ; conv(160->80, k1)+relu ; conv(80->80, k1)
    conv_kernel<3, true ><<<dim3(13, 2, 32), 256>>>(q_adj, Wq1, bq1, q1buf, 80, 160, 1600);
    conv_kernel<1, true ><<<dim3(13, 1, 32), 256>>>(q1buf, Wq2, bq2, q2buf, 160, 80, 1600);
    conv_kernel<1, false><<<dim3(13, 1, 32), 256>>>(q2buf, Wq3, bq3, q3buf, 80, 80, 1600);

    // fused attention: qk + log_softmax + prior + masked softmax
    int smem_bytes = (80 * 400 + 400 + 80 * 32) * 4;  // 139,840
    cudaFuncSetAttribute(attn_kernel, cudaFuncAttributeMaxDynamicSharedMemorySize, smem_bytes);
    attn_kernel<<<dim3(50, 32), 256, smem_bytes>>>(q3buf, kbuf, prior, mask, attn_out, logprob_out);
}

// round 5
// speedup vs baseline: 2.0732x; 2.0732x over previous
#include <cuda_runtime.h>
#include <cuda_bf16.h>
#include <mma.h>
#include <math.h>

using namespace nvcuda;

#define TEMP 0.0005f

// Shapes: B=32, C_MEL=80, C_TXT=512, C_ATT=80, T1=1600, T2=400
// GEMM view:  out[co,t] = bias[co] + sum_kk W[co,kk] * im2col[kk,t]

// ---------------- scratch ----------------
// fp32 scratch
#define F_SBK   0LL              // 32*512
#define F_SBQ   16384LL          // 32*80
#define F_KBUF  18944LL          // 32*80*400
#define F_Q3    1042944LL        // 32*80*1600
#define F_TOTAL 5138944LL
__device__ float g_f32[F_TOTAL];

// bf16 scratch (offsets all multiples of 8 elems -> 16B aligned)
#define H_WK1   0LL              // 1024*1536
#define H_WK2   1572864LL        // 80*1024
#define H_WQ1   1654784LL        // 160*256
#define H_WQ2   1695744LL        // 80*160
#define H_WQ3   1708544LL        // 80*96
#define H_IKEY  1716224LL        // 32*1536*448
#define H_K1    23736320LL       // 32*1024*448
#define H_IQ    38416384LL       // 32*256*1600
#define H_Q1    51523584LL       // 32*160*1600
#define H_Q2    59715584LL       // 32*96*1600 (rows 80..95 stay zero)
#define H_TOTAL 64630784LL
__device__ __align__(16) __nv_bfloat16 g_bf16[H_TOTAL];

// mask storage kind: 0 = int32 (0/1), 1 = float32, 2 = packed bytes
__device__ unsigned int g_mask_kind;

__global__ void detect_mask_kind(const unsigned int* __restrict__ mw)
{
    __shared__ unsigned int kinds;
    if (threadIdx.x == 0) kinds = 0u;
    __syncthreads();
    unsigned int local = 0u;
    for (int i = threadIdx.x; i < 3200; i += blockDim.x) {
        unsigned int v = mw[i];
        if (v == 0u) continue;
        else if (v == 1u) local |= 1u;
        else if (v == 0x3F800000u) local |= 2u;
        else local |= 4u;
    }
    atomicOr(&kinds, local);
    __syncthreads();
    if (threadIdx.x == 0) {
        unsigned int k = kinds;
        g_mask_kind = (k & 4u) ? 2u : ((k & 2u) ? 1u : 0u);
    }
}

// ---------------- speaker projection: sb[b][c] = spk[b].Wm[c] + bb[c] ----------------
__global__ __launch_bounds__(256) void spk_proj(
    const float* __restrict__ spk, const float* __restrict__ Wm,
    const float* __restrict__ bb, float* __restrict__ sb, int C)
{
    int b = blockIdx.x;
    const float* sp = spk + b * 512;
    for (int c = threadIdx.x; c < C; c += 256) {
        const float* wrow = Wm + c * 512;
        float s = bb[c];
        #pragma unroll 4
        for (int j = 0; j < 512; j++) s += sp[j] * wrow[j];
        sb[b * C + c] = s;
    }
}

// ---------------- weight fp32 -> bf16 with K padding ----------------
__global__ void convert_w(const float* __restrict__ src, __nv_bfloat16* __restrict__ dst,
                          int M, int K, int Kp)
{
    int n = M * Kp;
    for (int i = blockIdx.x * blockDim.x + threadIdx.x; i < n; i += gridDim.x * blockDim.x) {
        int m = i / Kp, k = i - m * Kp;
        dst[i] = (k < K) ? __float2bfloat16(src[m * K + k]) : __float2bfloat16(0.f);
    }
}

// ---------------- im2col (k=3, pad=1) + speaker bias, fp32 -> bf16 ----------------
// keys: [32][512][400] -> ikey [32][1536][448]
__global__ void im2col_k(const float* __restrict__ x, const float* __restrict__ sb,
                         __nv_bfloat16* __restrict__ dst)
{
    const long long n = 32LL * 1536 * 448;
    for (long long i = blockIdx.x * (long long)blockDim.x + threadIdx.x; i < n;
         i += (long long)gridDim.x * blockDim.x) {
        int t = (int)(i % 448);
        int kk = (int)((i / 448) % 1536);
        int b = (int)(i / (448LL * 1536));
        int ci = kk / 3, tap = kk - 3 * ci;
        int ts = t + tap - 1;
        float v = 0.f;
        if (t < 400 && ts >= 0 && ts < 400)
            v = x[((long long)b * 512 + ci) * 400 + ts] + sb[b * 512 + ci];
        dst[i] = __float2bfloat16(v);
    }
}

// queries: [32][80][1600] -> iq [32][256][1600] (rows 240..255 zero)
__global__ void im2col_q(const float* __restrict__ x, const float* __restrict__ sb,
                         __nv_bfloat16* __restrict__ dst)
{
    const long long n = 32LL * 256 * 1600;
    for (long long i = blockIdx.x * (long long)blockDim.x + threadIdx.x; i < n;
         i += (long long)gridDim.x * blockDim.x) {
        int t = (int)(i % 1600);
        int kk = (int)((i / 1600) % 256);
        int b = (int)(i / (1600LL * 256));
        float v = 0.f;
        if (kk < 240) {
            int ci = kk / 3, tap = kk - 3 * ci;
            int ts = t + tap - 1;
            if (ts >= 0 && ts < 1600)
                v = x[((long long)b * 80 + ci) * 1600 + ts] + sb[b * 80 + ci];
        }
        dst[i] = __float2bfloat16(v);
    }
}

// ---------------- bf16 WMMA GEMM ----------------
// C[b] = A[M x Kp] * B[b][Kp x Np]; store cols < Nvalid, rows < M, + bias (+relu)
#define BM 128
#define BN 64
#define BK 32

template<bool RELU, bool OUTBF16>
__global__ __launch_bounds__(256)
void gemm_wmma(const __nv_bfloat16* __restrict__ A, int Kp,
               const __nv_bfloat16* __restrict__ Bm, int Np,
               const float* __restrict__ bias,
               void* __restrict__ outp, int M, int Nvalid,
               long long out_bstride, int out_rstride)
{
    extern __shared__ char smc[];
    __nv_bfloat16* As = (__nv_bfloat16*)smc;                 // [BM][BK]
    __nv_bfloat16* Bs = (__nv_bfloat16*)(smc + BM * BK * 2); // [BK][BN]
    float* Cs = (float*)smc;                                 // [BM][BN] (reuse)

    int tid = threadIdx.x;
    int wid = tid >> 5;
    int n0 = blockIdx.x * BN;
    int m0 = blockIdx.y * BM;
    int b = blockIdx.z;
    const __nv_bfloat16* Bb = Bm + (long long)b * Kp * Np;

    wmma::fragment<wmma::accumulator, 16, 16, 16, float> c[2][2];
    #pragma unroll
    for (int i = 0; i < 2; i++)
        #pragma unroll
        for (int j = 0; j < 2; j++) wmma::fill_fragment(c[i][j], 0.f);

    int warp_m = (wid >> 1) * 32;
    int warp_n = (wid & 1) * 32;

    int am = tid >> 1;                 // A row handled by this thread
    int ak = (tid & 1) * 16;           // A k-offset
    int br = tid >> 3;                 // B row
    int bc = (tid & 7) * 8;            // B col

    for (int k0 = 0; k0 < Kp; k0 += BK) {
        uint4 v0 = {0, 0, 0, 0}, v1 = {0, 0, 0, 0};
        if (m0 + am < M) {
            const uint4* src = (const uint4*)(A + (long long)(m0 + am) * Kp + k0 + ak);
            v0 = src[0]; v1 = src[1];
        }
        *(uint4*)(As + am * BK + ak) = v0;
        *(uint4*)(As + am * BK + ak + 8) = v1;
        *(uint4*)(Bs + br * BN + bc) =
            *(const uint4*)(Bb + (long long)(k0 + br) * Np + n0 + bc);
        __syncthreads();

        #pragma unroll
        for (int kk = 0; kk < BK; kk += 16) {
            wmma::fragment<wmma::matrix_a, 16, 16, 16, __nv_bfloat16, wmma::row_major> a0, a1;
            wmma::fragment<wmma::matrix_b, 16, 16, 16, __nv_bfloat16, wmma::row_major> b0, b1;
            wmma::load_matrix_sync(a0, As + warp_m * BK + kk, BK);
            wmma::load_matrix_sync(a1, As + (warp_m + 16) * BK + kk, BK);
            wmma::load_matrix_sync(b0, Bs + kk * BN + warp_n, BN);
            wmma::load_matrix_sync(b1, Bs + kk * BN + warp_n + 16, BN);
            wmma::mma_sync(c[0][0], a0, b0, c[0][0]);
            wmma::mma_sync(c[0][1], a0, b1, c[0][1]);
            wmma::mma_sync(c[1][0], a1, b0, c[1][0]);
            wmma::mma_sync(c[1][1], a1, b1, c[1][1]);
        }
        __syncthreads();
    }

    #pragma unroll
    for (int i = 0; i < 2; i++)
        #pragma unroll
        for (int j = 0; j < 2; j++)
            wmma::store_matrix_sync(Cs + (warp_m + i * 16) * BN + warp_n + j * 16,
                                    c[i][j], BN, wmma::mem_row_major);
    __syncthreads();

    int n = tid & 63;
    int ng = n0 + n;
    for (int m2 = tid >> 6; m2 < BM; m2 += 4) {
        int mg = m0 + m2;
        if (mg < M && ng < Nvalid) {
            float v = Cs[m2 * BN + n] + bias[mg];
            if (RELU) v = fmaxf(v, 0.f);
            long long o = b * out_bstride + (long long)mg * out_rstride + ng;
            if (OUTBF16) ((__nv_bfloat16*)outp)[o] = __float2bfloat16(v);
            else ((float*)outp)[o] = v;
        }
    }
}

// ---------------- fused attention ----------------
__device__ __forceinline__ float warpMax(float v) {
    #pragma unroll
    for (int o = 16; o > 0; o >>= 1) v = fmaxf(v, __shfl_xor_sync(0xffffffffu, v, o));
    return v;
}
__device__ __forceinline__ float warpSum(float v) {
    #pragma unroll
    for (int o = 16; o > 0; o >>= 1) v += __shfl_xor_sync(0xffffffffu, v, o);
    return v;
}

__global__ __launch_bounds__(256) void attn_kernel(
    const float* __restrict__ q, const float* __restrict__ k,
    const float* __restrict__ prior, const void* __restrict__ maskp,
    float* __restrict__ attn_out, float* __restrict__ logprob_out)
{
    extern __shared__ float smem[];
    float* ksh  = smem;               // 80*400
    float* k2sh = smem + 80 * 400;    // 400
    float* qsh  = k2sh + 400;         // 80*32
    __shared__ unsigned char msh[400];

    int b = blockIdx.y;
    int t1_0 = blockIdx.x * 32;
    int tid = threadIdx.x;
    int w = tid >> 5;
    int lane = tid & 31;

    {
        unsigned int kind = g_mask_kind;
        if (kind == 0u) {
            const int* mi = (const int*)maskp;
            for (int s = tid; s < 400; s += 256) msh[s] = (mi[b * 400 + s] != 0);
        } else if (kind == 1u) {
            const float* mf = (const float*)maskp;
            for (int s = tid; s < 400; s += 256) msh[s] = (mf[b * 400 + s] != 0.f);
        } else {
            const unsigned char* mu = (const unsigned char*)maskp;
            for (int s = tid; s < 400; s += 256) msh[s] = (mu[b * 400 + s] != 0);
        }
    }

    const float* kb = k + (long long)b * 80 * 400;
    for (int i = tid; i < 80 * 400; i += 256) ksh[i] = kb[i];
    const float* qb = q + (long long)b * 80 * 1600;
    for (int i = tid; i < 80 * 32; i += 256) {
        int c = i >> 5; int t = i & 31;
        qsh[i] = qb[c * 1600 + t1_0 + t];
    }
    __syncthreads();
    for (int s = tid; s < 400; s += 256) {
        float a = 0.f;
        #pragma unroll 4
        for (int c = 0; c < 80; c++) { float v = ksh[c * 400 + s]; a += v * v; }
        k2sh[s] = a;
    }
    __syncthreads();

    float acc[4][13];
    #pragma unroll
    for (int jj = 0; jj < 4; jj++)
        #pragma unroll
        for (int i = 0; i < 13; i++) acc[jj][i] = 0.f;
    float q2v[4] = {0.f, 0.f, 0.f, 0.f};

    #pragma unroll 2
    for (int c = 0; c < 80; c++) {
        float kv[13];
        #pragma unroll
        for (int i = 0; i < 13; i++) {
            int s = i * 32 + lane;
            kv[i] = (s < 400) ? ksh[c * 400 + s] : 0.f;
        }
        float qv[4];
        #pragma unroll
        for (int jj = 0; jj < 4; jj++) qv[jj] = qsh[c * 32 + w * 4 + jj];
        #pragma unroll
        for (int jj = 0; jj < 4; jj++) {
            q2v[jj] += qv[jj] * qv[jj];
            #pragma unroll
            for (int i = 0; i < 13; i++)
                acc[jj][i] += qv[jj] * kv[i];
        }
    }

    #pragma unroll 1
    for (int jj = 0; jj < 4; jj++) {
        int t1 = t1_0 + w * 4 + jj;
        float sc[13];
        float m = -INFINITY;
        #pragma unroll
        for (int i = 0; i < 13; i++) {
            int s = i * 32 + lane;
            sc[i] = (s < 400) ? (-TEMP * (q2v[jj] + k2sh[s] - 2.f * acc[jj][i]))
                              : -INFINITY;
            m = fmaxf(m, sc[i]);
        }
        m = warpMax(m);
        float sum = 0.f;
        #pragma unroll
        for (int i = 0; i < 13; i++) sum += expf(sc[i] - m);
        sum = warpSum(sum);
        float lse = m + logf(sum);

        long long base = ((long long)b * 1600 + t1) * 400;
        float xm[13];
        float m2 = -INFINITY;
        #pragma unroll
        for (int i = 0; i < 13; i++) {
            int s = i * 32 + lane;
            if (s < 400) {
                float lp = sc[i] - lse + logf(prior[base + s] + 1e-8f);
                logprob_out[base + s] = lp;
                xm[i] = msh[s] ? -INFINITY : lp;
            } else xm[i] = -INFINITY;
            m2 = fmaxf(m2, xm[i]);
        }
        m2 = warpMax(m2);
        float s2 = 0.f;
        #pragma unroll
        for (int i = 0; i < 13; i++) {
            xm[i] = (xm[i] == -INFINITY) ? 0.f : expf(xm[i] - m2);
            s2 += xm[i];
        }
        s2 = warpSum(s2);
        float inv = 1.f / s2;
        #pragma unroll
        for (int i = 0; i < 13; i++) {
            int s = i * 32 + lane;
            if (s < 400) attn_out[base + s] = xm[i] * inv;
        }
    }
}

// ---------------- launch ----------------
extern "C" void kernel_launch(void* const* d_in, const int* in_sizes, int n_in,
                              void* d_out, int out_size)
{
    const float* queries = (const float*)d_in[0];
    const float* keys    = (const float*)d_in[1];
    const void*  mask    = (const void*)d_in[2];
    const float* prior   = (const float*)d_in[3];
    const float* spk     = (const float*)d_in[4];
    const float* Wk1 = (const float*)d_in[5];
    const float* bk1 = (const float*)d_in[6];
    const float* Wk2 = (const float*)d_in[7];
    const float* bk2 = (const float*)d_in[8];
    const float* Wq1 = (const float*)d_in[9];
    const float* bq1 = (const float*)d_in[10];
    const float* Wq2 = (const float*)d_in[11];
    const float* bq2 = (const float*)d_in[12];
    const float* Wq3 = (const float*)d_in[13];
    const float* bq3 = (const float*)d_in[14];
    const float* Wks = (const float*)d_in[15];
    const float* bks = (const float*)d_in[16];
    const float* Wqs = (const float*)d_in[17];
    const float* bqs = (const float*)d_in[18];

    float* out = (float*)d_out;
    float* attn_out = out;
    float* logprob_out = out + (long long)32 * 1600 * 400;

    float* f32 = nullptr;
    __nv_bfloat16* h = nullptr;
    cudaGetSymbolAddress((void**)&f32, g_f32);
    cudaGetSymbolAddress((void**)&h, g_bf16);

    float* sbk   = f32 + F_SBK;
    float* sbq   = f32 + F_SBQ;
    float* kbuf  = f32 + F_KBUF;
    float* q3buf = f32 + F_Q3;

    __nv_bfloat16* Wk1b = h + H_WK1;
    __nv_bfloat16* Wk2b = h + H_WK2;
    __nv_bfloat16* Wq1b = h + H_WQ1;
    __nv_bfloat16* Wq2b = h + H_WQ2;
    __nv_bfloat16* Wq3b = h + H_WQ3;
    __nv_bfloat16* ikey = h + H_IKEY;
    __nv_bfloat16* k1b  = h + H_K1;
    __nv_bfloat16* iq   = h + H_IQ;
    __nv_bfloat16* q1b  = h + H_Q1;
    __nv_bfloat16* q2b  = h + H_Q2;

    detect_mask_kind<<<1, 256>>>((const unsigned int*)mask);

    spk_proj<<<32, 256>>>(spk, Wks, bks, sbk, 512);
    spk_proj<<<32, 256>>>(spk, Wqs, bqs, sbq, 80);

    convert_w<<<2048, 256>>>(Wk1, Wk1b, 1024, 1536, 1536);
    convert_w<<<320, 256>>>(Wk2, Wk2b, 80, 1024, 1024);
    convert_w<<<160, 256>>>(Wq1, Wq1b, 160, 240, 256);
    convert_w<<<50, 256>>>(Wq2, Wq2b, 80, 160, 160);
    convert_w<<<30, 256>>>(Wq3, Wq3b, 80, 80, 96);

    im2col_k<<<8192, 256>>>(keys, sbk, ikey);
    im2col_q<<<8192, 256>>>(queries, sbq, iq);

    const int GS = 32768;  // gemm smem (C tile fp32 128x64)
    // K path
    gemm_wmma<true,  true ><<<dim3(7, 8, 32), 256, GS>>>(Wk1b, 1536, ikey, 448, bk1,
                                                          k1b, 1024, 400, 458752LL, 448);
    gemm_wmma<false, false><<<dim3(7, 1, 32), 256, GS>>>(Wk2b, 1024, k1b, 448, bk2,
                                                          kbuf, 80, 400, 32000LL, 400);
    // Q path
    gemm_wmma<true,  true ><<<dim3(25, 2, 32), 256, GS>>>(Wq1b, 256, iq, 1600, bq1,
                                                           q1b, 160, 1600, 256000LL, 1600);
    gemm_wmma<true,  true ><<<dim3(25, 1, 32), 256, GS>>>(Wq2b, 160, q1b, 1600, bq2,
                                                           q2b, 80, 1600, 153600LL, 1600);
    gemm_wmma<false, false><<<dim3(25, 1, 32), 256, GS>>>(Wq3b, 96, q2b, 1600, bq3,
                                                           q3buf, 80, 1600, 128000LL, 1600);

    // fused attention
    int smem_bytes = (80 * 400 + 400 + 80 * 32) * 4;  // 139,840
    cudaFuncSetAttribute(attn_kernel, cudaFuncAttributeMaxDynamicSharedMemorySize, smem_bytes);
    attn_kernel<<<dim3(50, 32), 256, smem_bytes>>>(q3buf, kbuf, prior, mask, attn_out, logprob_out);
}

// round 8
// speedup vs baseline: 3.8772x; 1.8701x over previous
#include <cuda_runtime.h>
#include <cuda_bf16.h>
#include <mma.h>
#include <math.h>
#include <stdint.h>

using namespace nvcuda;

#define TEMP 0.0005f

// Shapes: B=32, C_MEL=80, C_TXT=512, C_ATT=80, T1=1600, T2=400
// All convs as single flat GEMMs: C[M, 32*Tpad] = W[M,K] @ im2col[K, 32*Tpad]

// ---------------- fp32 scratch ----------------
#define F_SBK   0LL              // 32*512
#define F_SBQ   16384LL          // 32*80
#define F_KBUF  18944LL          // 32*80*400
#define F_Q3    1042944LL        // 32*80*1600
#define F_TOTAL 5138944LL
__device__ float g_f32[F_TOTAL];

// ---------------- bf16 scratch (all offsets multiple of 8 elems) ----------------
#define H_WK1   0LL              // 1024*1536
#define H_WK2   1572864LL        // 80*1024
#define H_WQ1   1654784LL        // 160*256
#define H_WQ2   1695744LL        // 80*160
#define H_WQ3   1708544LL        // 80*96
#define H_IKEY  1716224LL        // 1536*14336
#define H_K1    23736320LL       // 1024*14336
#define H_IQ    38416384LL       // 256*51200
#define H_Q1    51523584LL       // 160*51200
#define H_Q2    59715584LL       // 96*51200 (rows 80..95 never written -> stay 0)
#define H_TOTAL 64630784LL
__device__ __align__(16) __nv_bfloat16 g_bf16[H_TOTAL];

// mask storage kind: 0 = int32 (0/1), 1 = float32, 2 = packed bytes
__device__ unsigned int g_mask_kind;

__global__ void detect_mask_kind(const unsigned int* __restrict__ mw)
{
    __shared__ unsigned int kinds;
    if (threadIdx.x == 0) kinds = 0u;
    __syncthreads();
    unsigned int local = 0u;
    for (int i = threadIdx.x; i < 3200; i += blockDim.x) {
        unsigned int v = mw[i];
        if (v == 0u) continue;
        else if (v == 1u) local |= 1u;
        else if (v == 0x3F800000u) local |= 2u;
        else local |= 4u;
    }
    atomicOr(&kinds, local);
    __syncthreads();
    if (threadIdx.x == 0) {
        unsigned int k = kinds;
        g_mask_kind = (k & 4u) ? 2u : ((k & 2u) ? 1u : 0u);
    }
}

// ---------------- speaker projection ----------------
__global__ __launch_bounds__(256) void spk_proj(
    const float* __restrict__ spk, const float* __restrict__ Wm,
    const float* __restrict__ bb, float* __restrict__ sb, int C)
{
    int b = blockIdx.x;
    int c = blockIdx.y * 256 + threadIdx.x;
    if (c >= C) return;
    const float* sp = spk + b * 512;
    const float4* wrow = (const float4*)(Wm + c * 512);
    const float4* sp4 = (const float4*)sp;
    float s = bb[c];
    #pragma unroll 4
    for (int j = 0; j < 128; j++) {
        float4 w = wrow[j], x = sp4[j];
        s += w.x * x.x + w.y * x.y + w.z * x.z + w.w * x.w;
    }
    sb[b * C + c] = s;
}

// ---------------- weight fp32 -> bf16 with K padding ----------------
__global__ void convert_w(const float* __restrict__ src, __nv_bfloat16* __restrict__ dst,
                          int M, int K, int Kp)
{
    int n = M * Kp;
    for (int i = blockIdx.x * blockDim.x + threadIdx.x; i < n; i += gridDim.x * blockDim.x) {
        int m = i / Kp, k = i - m * Kp;
        dst[i] = (k < K) ? __float2bfloat16(src[m * K + k]) : __float2bfloat16(0.f);
    }
}

// ---------------- im2col (k=3, pad=1) + speaker bias, flat [K][32*Tpad] ----------------
// keys: [32][512][400] -> ikey[kk][b*448+t]
__global__ void im2col_k(const float* __restrict__ x, const float* __restrict__ sb,
                         __nv_bfloat16* __restrict__ dst)
{
    const long long n = 1536LL * 14336;
    for (long long i = blockIdx.x * (long long)blockDim.x + threadIdx.x; i < n;
         i += (long long)gridDim.x * blockDim.x) {
        int col = (int)(i % 14336);
        int kk = (int)(i / 14336);
        int b = col / 448, t = col - b * 448;
        int ci = kk / 3, tap = kk - 3 * ci;
        int ts = t + tap - 1;
        float v = 0.f;
        if (t < 400 && ts >= 0 && ts < 400)
            v = x[((long long)b * 512 + ci) * 400 + ts] + sb[b * 512 + ci];
        dst[i] = __float2bfloat16(v);
    }
}

// queries: [32][80][1600] -> iq[kk][b*1600+t], rows 240..255 zero
__global__ void im2col_q(const float* __restrict__ x, const float* __restrict__ sb,
                         __nv_bfloat16* __restrict__ dst)
{
    const long long n = 256LL * 51200;
    for (long long i = blockIdx.x * (long long)blockDim.x + threadIdx.x; i < n;
         i += (long long)gridDim.x * blockDim.x) {
        int col = (int)(i % 51200);
        int kk = (int)(i / 51200);
        int b = col / 1600, t = col - b * 1600;
        float v = 0.f;
        if (kk < 240) {
            int ci = kk / 3, tap = kk - 3 * ci;
            int ts = t + tap - 1;
            if (ts >= 0 && ts < 1600)
                v = x[((long long)b * 80 + ci) * 1600 + ts] + sb[b * 80 + ci];
        }
        dst[i] = __float2bfloat16(v);
    }
}

// ---------------- pipelined bf16 WMMA GEMM ----------------
// 128x128 block tile, BK=32, 3-stage cp.async, 8 warps in 2(m) x 4(n), 64x32 warp tiles.
#define GBM 128
#define GBN 128
#define GBK 32
#define ASTR 56    // As row stride (elems): bank-quads 0,28,24,20,16,12,8,4 (disjoint)
#define BSTR 152   // Bs row stride: quads 0,12,24,4,16,28,8,20 (disjoint)
#define CSTR 132
#define ASZ (GBM * ASTR * 2)          // 14336 B
#define BSZ (GBK * BSTR * 2)          // 9728 B
#define STGB (ASZ + BSZ)              // 24064 B
#define GEMM_SMEM (3 * STGB)          // 72192 B (Cs 128*132*4=67584 fits)

__device__ __forceinline__ void ldgsts16(unsigned int dst, const void* src, bool p) {
    asm volatile("cp.async.cg.shared.global [%0], [%1], 16, %2;\n"
                 :: "r"(dst), "l"(src), "r"(p ? 16 : 0));
}
__device__ __forceinline__ void cp_commit() { asm volatile("cp.async.commit_group;\n"); }
template<int N> __device__ __forceinline__ void cp_wait() {
    asm volatile("cp.async.wait_group %0;\n" :: "n"(N));
}

// MODE 0: bf16 flat out[m*Ntot+col]; MODE 1: f32 out[(b*Cout+m)*Tvalid+t], col=b*Tpad+t
template<bool RELU, int MODE>
__global__ __launch_bounds__(256)
void gemm_bf16(const __nv_bfloat16* __restrict__ A, int Kp,
               const __nv_bfloat16* __restrict__ Bm, long long Ntot,
               const float* __restrict__ bias, void* __restrict__ outp,
               int M, int Tpad, int Tvalid, int Cout)
{
    extern __shared__ char smc[];
    unsigned int sbase = (unsigned int)__cvta_generic_to_shared(smc);

    int tid = threadIdx.x;
    int wid = tid >> 5;
    int n0 = blockIdx.x * GBN;
    int m0 = blockIdx.y * GBM;

    int wm = (wid >> 2) * 64;      // 2 warp rows
    int wn = (wid & 3) * 32;       // 4 warp cols

    wmma::fragment<wmma::accumulator, 16, 16, 16, float> c[4][2];
    #pragma unroll
    for (int i = 0; i < 4; i++)
        #pragma unroll
        for (int j = 0; j < 2; j++) wmma::fill_fragment(c[i][j], 0.f);

    int nk = Kp / GBK;

    // stage loader
    auto load_stage = [&](int slot, int kc) {
        unsigned int sa = sbase + slot * STGB;
        // A: 128 rows x 32 cols = 512 x 16B chunks
        #pragma unroll
        for (int it = 0; it < 2; it++) {
            int cch = tid + it * 256;
            int row = cch >> 2;
            int coff = (cch & 3) << 3;
            bool pred = (m0 + row) < M;
            int rowc = pred ? (m0 + row) : (M - 1);
            ldgsts16(sa + row * (ASTR * 2) + ((cch & 3) << 4),
                     A + (long long)rowc * Kp + kc + coff, pred);
        }
        // B: 32 rows x 128 cols = 512 x 16B chunks
        unsigned int sb2 = sa + ASZ;
        #pragma unroll
        for (int it = 0; it < 2; it++) {
            int cch = tid + it * 256;
            int row = cch >> 4;
            int coff = (cch & 15) << 3;
            ldgsts16(sb2 + row * (BSTR * 2) + ((cch & 15) << 4),
                     Bm + (long long)(kc + row) * Ntot + n0 + coff, true);
        }
    };

    // prologue: stages 0,1
    load_stage(0, 0); cp_commit();
    load_stage(1, GBK); cp_commit();

    for (int i = 0; i < nk; i++) {
        cp_wait<1>();
        __syncthreads();
        int pf = i + 2;
        if (pf < nk) load_stage(pf % 3, pf * GBK);
        cp_commit();

        const __nv_bfloat16* As = (const __nv_bfloat16*)(smc + (i % 3) * STGB);
        const __nv_bfloat16* Bs = (const __nv_bfloat16*)(smc + (i % 3) * STGB + ASZ);
        #pragma unroll
        for (int kk = 0; kk < GBK; kk += 16) {
            wmma::fragment<wmma::matrix_a, 16, 16, 16, __nv_bfloat16, wmma::row_major> a[4];
            wmma::fragment<wmma::matrix_b, 16, 16, 16, __nv_bfloat16, wmma::row_major> b[2];
            #pragma unroll
            for (int r = 0; r < 4; r++)
                wmma::load_matrix_sync(a[r], As + (wm + 16 * r) * ASTR + kk, ASTR);
            #pragma unroll
            for (int j = 0; j < 2; j++)
                wmma::load_matrix_sync(b[j], Bs + kk * BSTR + wn + 16 * j, BSTR);
            #pragma unroll
            for (int r = 0; r < 4; r++)
                #pragma unroll
                for (int j = 0; j < 2; j++)
                    wmma::mma_sync(c[r][j], a[r], b[j], c[r][j]);
        }
    }

    cp_wait<0>();
    __syncthreads();

    float* Cs = (float*)smc;
    #pragma unroll
    for (int r = 0; r < 4; r++)
        #pragma unroll
        for (int j = 0; j < 2; j++)
            wmma::store_matrix_sync(Cs + (wm + 16 * r) * CSTR + wn + 16 * j,
                                    c[r][j], CSTR, wmma::mem_row_major);
    __syncthreads();

    int n = tid & 127;
    int col = n0 + n;
    int b = 0, t = 0;
    if (MODE == 1) { b = col / Tpad; t = col - b * Tpad; }
    for (int m2 = tid >> 7; m2 < GBM; m2 += 2) {
        int mg = m0 + m2;
        if (mg >= M) break;
        float v = Cs[m2 * CSTR + n] + bias[mg];
        if (RELU) v = fmaxf(v, 0.f);
        if (MODE == 0) {
            ((__nv_bfloat16*)outp)[(long long)mg * Ntot + col] = __float2bfloat16(v);
        } else {
            if (t < Tvalid)
                ((float*)outp)[((long long)b * Cout + mg) * Tvalid + t] = v;
        }
    }
}

// ---------------- fused attention ----------------
__device__ __forceinline__ float warpMax(float v) {
    #pragma unroll
    for (int o = 16; o > 0; o >>= 1) v = fmaxf(v, __shfl_xor_sync(0xffffffffu, v, o));
    return v;
}
__device__ __forceinline__ float warpSum(float v) {
    #pragma unroll
    for (int o = 16; o > 0; o >>= 1) v += __shfl_xor_sync(0xffffffffu, v, o);
    return v;
}

__global__ __launch_bounds__(256) void attn_kernel(
    const float* __restrict__ q, const float* __restrict__ k,
    const float* __restrict__ prior, const void* __restrict__ maskp,
    float* __restrict__ attn_out, float* __restrict__ logprob_out)
{
    extern __shared__ float smem[];
    float* ksh  = smem;               // 80*400
    float* k2sh = smem + 80 * 400;    // 400
    float* qsh  = k2sh + 400;         // 80*32
    __shared__ unsigned char msh[400];

    int b = blockIdx.y;
    int t1_0 = blockIdx.x * 32;
    int tid = threadIdx.x;
    int w = tid >> 5;
    int lane = tid & 31;

    {
        unsigned int kind = g_mask_kind;
        if (kind == 0u) {
            const int* mi = (const int*)maskp;
            for (int s = tid; s < 400; s += 256) msh[s] = (mi[b * 400 + s] != 0);
        } else if (kind == 1u) {
            const float* mf = (const float*)maskp;
            for (int s = tid; s < 400; s += 256) msh[s] = (mf[b * 400 + s] != 0.f);
        } else {
            const unsigned char* mu = (const unsigned char*)maskp;
            for (int s = tid; s < 400; s += 256) msh[s] = (mu[b * 400 + s] != 0);
        }
    }

    const float* kb = k + (long long)b * 80 * 400;
    for (int i = tid; i < 80 * 400; i += 256) ksh[i] = kb[i];
    const float* qb = q + (long long)b * 80 * 1600;
    for (int i = tid; i < 80 * 32; i += 256) {
        int c = i >> 5; int t = i & 31;
        qsh[i] = qb[c * 1600 + t1_0 + t];
    }
    __syncthreads();
    for (int s = tid; s < 400; s += 256) {
        float a = 0.f;
        #pragma unroll 4
        for (int c = 0; c < 80; c++) { float v = ksh[c * 400 + s]; a += v * v; }
        k2sh[s] = a;
    }
    __syncthreads();

    float acc[4][13];
    #pragma unroll
    for (int jj = 0; jj < 4; jj++)
        #pragma unroll
        for (int i = 0; i < 13; i++) acc[jj][i] = 0.f;
    float q2v[4] = {0.f, 0.f, 0.f, 0.f};

    #pragma unroll 2
    for (int c = 0; c < 80; c++) {
        float kv[13];
        #pragma unroll
        for (int i = 0; i < 13; i++) {
            int s = i * 32 + lane;
            kv[i] = (s < 400) ? ksh[c * 400 + s] : 0.f;
        }
        float qv[4];
        #pragma unroll
        for (int jj = 0; jj < 4; jj++) qv[jj] = qsh[c * 32 + w * 4 + jj];
        #pragma unroll
        for (int jj = 0; jj < 4; jj++) {
            q2v[jj] += qv[jj] * qv[jj];
            #pragma unroll
            for (int i = 0; i < 13; i++)
                acc[jj][i] += qv[jj] * kv[i];
        }
    }

    #pragma unroll 1
    for (int jj = 0; jj < 4; jj++) {
        int t1 = t1_0 + w * 4 + jj;
        float sc[13];
        float m = -INFINITY;
        #pragma unroll
        for (int i = 0; i < 13; i++) {
            int s = i * 32 + lane;
            sc[i] = (s < 400) ? (-TEMP * (q2v[jj] + k2sh[s] - 2.f * acc[jj][i]))
                              : -INFINITY;
            m = fmaxf(m, sc[i]);
        }
        m = warpMax(m);
        float sum = 0.f;
        #pragma unroll
        for (int i = 0; i < 13; i++) sum += expf(sc[i] - m);
        sum = warpSum(sum);
        float lse = m + logf(sum);

        long long base = ((long long)b * 1600 + t1) * 400;
        float xm[13];
        float m2 = -INFINITY;
        #pragma unroll
        for (int i = 0; i < 13; i++) {
            int s = i * 32 + lane;
            if (s < 400) {
                float lp = sc[i] - lse + logf(prior[base + s] + 1e-8f);
                logprob_out[base + s] = lp;
                xm[i] = msh[s] ? -INFINITY : lp;
            } else xm[i] = -INFINITY;
            m2 = fmaxf(m2, xm[i]);
        }
        m2 = warpMax(m2);
        float s2 = 0.f;
        #pragma unroll
        for (int i = 0; i < 13; i++) {
            xm[i] = (xm[i] == -INFINITY) ? 0.f : expf(xm[i] - m2);
            s2 += xm[i];
        }
        s2 = warpSum(s2);
        float inv = 1.f / s2;
        #pragma unroll
        for (int i = 0; i < 13; i++) {
            int s = i * 32 + lane;
            if (s < 400) attn_out[base + s] = xm[i] * inv;
        }
    }
}

// ---------------- launch ----------------
extern "C" void kernel_launch(void* const* d_in, const int* in_sizes, int n_in,
                              void* d_out, int out_size)
{
    const float* queries = (const float*)d_in[0];
    const float* keys    = (const float*)d_in[1];
    const void*  mask    = (const void*)d_in[2];
    const float* prior   = (const float*)d_in[3];
    const float* spk     = (const float*)d_in[4];
    const float* Wk1 = (const float*)d_in[5];
    const float* bk1 = (const float*)d_in[6];
    const float* Wk2 = (const float*)d_in[7];
    const float* bk2 = (const float*)d_in[8];
    const float* Wq1 = (const float*)d_in[9];
    const float* bq1 = (const float*)d_in[10];
    const float* Wq2 = (const float*)d_in[11];
    const float* bq2 = (const float*)d_in[12];
    const float* Wq3 = (const float*)d_in[13];
    const float* bq3 = (const float*)d_in[14];
    const float* Wks = (const float*)d_in[15];
    const float* bks = (const float*)d_in[16];
    const float* Wqs = (const float*)d_in[17];
    const float* bqs = (const float*)d_in[18];

    float* out = (float*)d_out;
    float* attn_out = out;
    float* logprob_out = out + (long long)32 * 1600 * 400;

    float* f32 = nullptr;
    __nv_bfloat16* h = nullptr;
    cudaGetSymbolAddress((void**)&f32, g_f32);
    cudaGetSymbolAddress((void**)&h, g_bf16);

    float* sbk   = f32 + F_SBK;
    float* sbq   = f32 + F_SBQ;
    float* kbuf  = f32 + F_KBUF;
    float* q3buf = f32 + F_Q3;

    __nv_bfloat16* Wk1b = h + H_WK1;
    __nv_bfloat16* Wk2b = h + H_WK2;
    __nv_bfloat16* Wq1b = h + H_WQ1;
    __nv_bfloat16* Wq2b = h + H_WQ2;
    __nv_bfloat16* Wq3b = h + H_WQ3;
    __nv_bfloat16* ikey = h + H_IKEY;
    __nv_bfloat16* k1b  = h + H_K1;
    __nv_bfloat16* iq   = h + H_IQ;
    __nv_bfloat16* q1b  = h + H_Q1;
    __nv_bfloat16* q2b  = h + H_Q2;

    detect_mask_kind<<<1, 256>>>((const unsigned int*)mask);

    spk_proj<<<dim3(32, 2), 256>>>(spk, Wks, bks, sbk, 512);
    spk_proj<<<dim3(32, 1), 256>>>(spk, Wqs, bqs, sbq, 80);

    convert_w<<<2048, 256>>>(Wk1, Wk1b, 1024, 1536, 1536);
    convert_w<<<320, 256>>>(Wk2, Wk2b, 80, 1024, 1024);
    convert_w<<<160, 256>>>(Wq1, Wq1b, 160, 240, 256);
    convert_w<<<50, 256>>>(Wq2, Wq2b, 80, 160, 160);
    convert_w<<<30, 256>>>(Wq3, Wq3b, 80, 80, 96);

    im2col_k<<<8192, 256>>>(keys, sbk, ikey);
    im2col_q<<<8192, 256>>>(queries, sbq, iq);

    cudaFuncSetAttribute((const void*)&gemm_bf16<true, 0>,
                         cudaFuncAttributeMaxDynamicSharedMemorySize, GEMM_SMEM);
    cudaFuncSetAttribute((const void*)&gemm_bf16<false, 1>,
                         cudaFuncAttributeMaxDynamicSharedMemorySize, GEMM_SMEM);

    // K path: [1024 x 14336 x 1536] relu -> [80 x 14336 x 1024] -> kbuf f32
    gemm_bf16<true, 0><<<dim3(112, 8), 256, GEMM_SMEM>>>(
        Wk1b, 1536, ikey, 14336LL, bk1, k1b, 1024, 0, 0, 0);
    gemm_bf16<false, 1><<<dim3(112, 1), 256, GEMM_SMEM>>>(
        Wk2b, 1024, k1b, 14336LL, bk2, kbuf, 80, 448, 400, 80);

    // Q path: [160 x 51200 x 256] relu -> [80 x 51200 x 160] relu -> [80 x 51200 x 96] f32
    gemm_bf16<true, 0><<<dim3(400, 2), 256, GEMM_SMEM>>>(
        Wq1b, 256, iq, 51200LL, bq1, q1b, 160, 0, 0, 0);
    gemm_bf16<true, 0><<<dim3(400, 1), 256, GEMM_SMEM>>>(
        Wq2b, 160, q1b, 51200LL, bq2, q2b, 80, 0, 0, 0);
    gemm_bf16<false, 1><<<dim3(400, 1), 256, GEMM_SMEM>>>(
        Wq3b, 96, q2b, 51200LL, bq3, q3buf, 80, 1600, 1600, 80);

    // fused attention
    int smem_bytes = (80 * 400 + 400 + 80 * 32) * 4;  // 139,840
    cudaFuncSetAttribute(attn_kernel, cudaFuncAttributeMaxDynamicSharedMemorySize, smem_bytes);
    attn_kernel<<<dim3(50, 32), 256, smem_bytes>>>(q3buf, kbuf, prior, mask, attn_out, logprob_out);
}

// round 10
// speedup vs baseline: 5.1015x; 1.3157x over previous
#include <cuda_runtime.h>
#include <cuda_bf16.h>
#include <mma.h>
#include <math.h>
#include <stdint.h>

using namespace nvcuda;

#define TEMP 0.0005f

// Shapes: B=32, C_MEL=80, C_TXT=512, C_ATT=80, T1=1600, T2=400
// Convs as flat GEMMs: C[M, 32*Tpad] = W[M,K] @ im2col[K, 32*Tpad]

// ---------------- fp32 scratch ----------------
#define F_SBK   0LL              // 32*512
#define F_SBQ   16384LL          // 32*80
#define F_TOTAL 18944LL
__device__ float g_f32[F_TOTAL];

// ---------------- bf16 scratch ----------------
#define H_WK1   0LL              // 1024*1536
#define H_WK2   1572864LL        // 80*1024
#define H_WQ1   1654784LL        // 160*256
#define H_WQ2   1695744LL        // 80*160
#define H_WQ3   1708544LL        // 80*96
#define H_WEND  1716224LL
#define H_IKEY  1716224LL        // 1536*14336
#define H_K1    23736320LL       // 1024*14336
#define H_IQ    38416384LL       // 256*51200
#define H_Q1    51523584LL       // 160*51200
#define H_Q2    59715584LL       // 96*51200 (rows 80..95 stay 0)
#define H_KOUT  64630784LL       // 80*14336
#define H_Q3    65777664LL       // 80*51200
#define H_TOTAL 69873664LL
__device__ __align__(16) __nv_bfloat16 g_bf16[H_TOTAL];

// mask storage kind: 0 = int32 (0/1), 1 = float32, 2 = packed bytes
__device__ unsigned int g_mask_kind;

__global__ void detect_mask_kind(const unsigned int* __restrict__ mw)
{
    __shared__ unsigned int kinds;
    if (threadIdx.x == 0) kinds = 0u;
    __syncthreads();
    unsigned int local = 0u;
    for (int i = threadIdx.x; i < 3200; i += blockDim.x) {
        unsigned int v = mw[i];
        if (v == 0u) continue;
        else if (v == 1u) local |= 1u;
        else if (v == 0x3F800000u) local |= 2u;
        else local |= 4u;
    }
    atomicOr(&kinds, local);
    __syncthreads();
    if (threadIdx.x == 0) {
        unsigned int k = kinds;
        g_mask_kind = (k & 4u) ? 2u : ((k & 2u) ? 1u : 0u);
    }
}

// ---------------- speaker projection ----------------
__global__ __launch_bounds__(256) void spk_proj(
    const float* __restrict__ spk, const float* __restrict__ Wm,
    const float* __restrict__ bb, float* __restrict__ sb, int C)
{
    int b = blockIdx.x;
    int c = blockIdx.y * 256 + threadIdx.x;
    if (c >= C) return;
    const float* sp = spk + b * 512;
    const float4* wrow = (const float4*)(Wm + c * 512);
    const float4* sp4 = (const float4*)sp;
    float s = bb[c];
    #pragma unroll 4
    for (int j = 0; j < 128; j++) {
        float4 w = wrow[j], x = sp4[j];
        s += w.x * x.x + w.y * x.y + w.z * x.z + w.w * x.w;
    }
    sb[b * C + c] = s;
}

// ---------------- all weight conversions in one kernel ----------------
// dst segments are contiguous at g_bf16[0 .. H_WEND)
__global__ void convert_all(const float* __restrict__ Wk1, const float* __restrict__ Wk2,
                            const float* __restrict__ Wq1, const float* __restrict__ Wq2,
                            const float* __restrict__ Wq3, __nv_bfloat16* __restrict__ dst)
{
    for (long long i = blockIdx.x * (long long)blockDim.x + threadIdx.x; i < H_WEND;
         i += (long long)gridDim.x * blockDim.x) {
        const float* src; long long li; int K, Kp;
        if (i < H_WK2)      { src = Wk1; li = i - H_WK1; K = 1536; Kp = 1536; }
        else if (i < H_WQ1) { src = Wk2; li = i - H_WK2; K = 1024; Kp = 1024; }
        else if (i < H_WQ2) { src = Wq1; li = i - H_WQ1; K = 240;  Kp = 256; }
        else if (i < H_WQ3) { src = Wq2; li = i - H_WQ2; K = 160;  Kp = 160; }
        else                { src = Wq3; li = i - H_WQ3; K = 80;   Kp = 96; }
        long long m = li / Kp; int k = (int)(li - m * Kp);
        dst[i] = (k < K) ? __float2bfloat16(src[m * K + k]) : __float2bfloat16(0.f);
    }
}

// ---------------- im2col (k=3, pad=1) + speaker bias ----------------
__global__ void im2col_k(const float* __restrict__ x, const float* __restrict__ sb,
                         __nv_bfloat16* __restrict__ dst)
{
    const long long n = 1536LL * 14336;
    for (long long i = blockIdx.x * (long long)blockDim.x + threadIdx.x; i < n;
         i += (long long)gridDim.x * blockDim.x) {
        int col = (int)(i % 14336);
        int kk = (int)(i / 14336);
        int b = col / 448, t = col - b * 448;
        int ci = kk / 3, tap = kk - 3 * ci;
        int ts = t + tap - 1;
        float v = 0.f;
        if (t < 400 && ts >= 0 && ts < 400)
            v = x[((long long)b * 512 + ci) * 400 + ts] + sb[b * 512 + ci];
        dst[i] = __float2bfloat16(v);
    }
}

__global__ void im2col_q(const float* __restrict__ x, const float* __restrict__ sb,
                         __nv_bfloat16* __restrict__ dst)
{
    const long long n = 256LL * 51200;
    for (long long i = blockIdx.x * (long long)blockDim.x + threadIdx.x; i < n;
         i += (long long)gridDim.x * blockDim.x) {
        int col = (int)(i % 51200);
        int kk = (int)(i / 51200);
        int b = col / 1600, t = col - b * 1600;
        float v = 0.f;
        if (kk < 240) {
            int ci = kk / 3, tap = kk - 3 * ci;
            int ts = t + tap - 1;
            if (ts >= 0 && ts < 1600)
                v = x[((long long)b * 80 + ci) * 1600 + ts] + sb[b * 80 + ci];
        }
        dst[i] = __float2bfloat16(v);
    }
}

// ---------------- pipelined bf16 WMMA GEMM (bf16 flat output) ----------------
#define GBM 128
#define GBN 128
#define GBK 32
#define ASTR 56
#define BSTR 152
#define ASZ (GBM * ASTR * 2)
#define BSZ (GBK * BSTR * 2)
#define STGB (ASZ + BSZ)
#define GEMM_SMEM (3 * STGB)

__device__ __forceinline__ void ldgsts16(unsigned int dst, const void* src, bool p) {
    asm volatile("cp.async.cg.shared.global [%0], [%1], 16, %2;\n"
                 :: "r"(dst), "l"(src), "r"(p ? 16 : 0));
}
__device__ __forceinline__ void cp_commit() { asm volatile("cp.async.commit_group;\n"); }
template<int N> __device__ __forceinline__ void cp_wait() {
    asm volatile("cp.async.wait_group %0;\n" :: "n"(N));
}

template<bool RELU>
__global__ __launch_bounds__(256)
void gemm_bf16(const __nv_bfloat16* __restrict__ A, int Kp,
               const __nv_bfloat16* __restrict__ Bm, long long Ntot,
               const float* __restrict__ bias, __nv_bfloat16* __restrict__ outp, int M)
{
    extern __shared__ char smc[];
    unsigned int sbase = (unsigned int)__cvta_generic_to_shared(smc);

    int tid = threadIdx.x;
    int wid = tid >> 5;
    int n0 = blockIdx.x * GBN;
    int m0 = blockIdx.y * GBM;

    int wm = (wid >> 2) * 64;
    int wn = (wid & 3) * 32;

    wmma::fragment<wmma::accumulator, 16, 16, 16, float> c[4][2];
    #pragma unroll
    for (int i = 0; i < 4; i++)
        #pragma unroll
        for (int j = 0; j < 2; j++) wmma::fill_fragment(c[i][j], 0.f);

    int nk = Kp / GBK;

    auto load_stage = [&](int slot, int kc) {
        unsigned int sa = sbase + slot * STGB;
        #pragma unroll
        for (int it = 0; it < 2; it++) {
            int cch = tid + it * 256;
            int row = cch >> 2;
            int coff = (cch & 3) << 3;
            bool pred = (m0 + row) < M;
            int rowc = pred ? (m0 + row) : (M - 1);
            ldgsts16(sa + row * (ASTR * 2) + ((cch & 3) << 4),
                     A + (long long)rowc * Kp + kc + coff, pred);
        }
        unsigned int sb2 = sa + ASZ;
        #pragma unroll
        for (int it = 0; it < 2; it++) {
            int cch = tid + it * 256;
            int row = cch >> 4;
            int coff = (cch & 15) << 3;
            ldgsts16(sb2 + row * (BSTR * 2) + ((cch & 15) << 4),
                     Bm + (long long)(kc + row) * Ntot + n0 + coff, true);
        }
    };

    load_stage(0, 0); cp_commit();
    load_stage(1, GBK); cp_commit();

    for (int i = 0; i < nk; i++) {
        cp_wait<1>();
        __syncthreads();
        int pf = i + 2;
        if (pf < nk) load_stage(pf % 3, pf * GBK);
        cp_commit();

        const __nv_bfloat16* As = (const __nv_bfloat16*)(smc + (i % 3) * STGB);
        const __nv_bfloat16* Bs = (const __nv_bfloat16*)(smc + (i % 3) * STGB + ASZ);
        #pragma unroll
        for (int kk = 0; kk < GBK; kk += 16) {
            wmma::fragment<wmma::matrix_a, 16, 16, 16, __nv_bfloat16, wmma::row_major> a[4];
            wmma::fragment<wmma::matrix_b, 16, 16, 16, __nv_bfloat16, wmma::row_major> b[2];
            #pragma unroll
            for (int r = 0; r < 4; r++)
                wmma::load_matrix_sync(a[r], As + (wm + 16 * r) * ASTR + kk, ASTR);
            #pragma unroll
            for (int j = 0; j < 2; j++)
                wmma::load_matrix_sync(b[j], Bs + kk * BSTR + wn + 16 * j, BSTR);
            #pragma unroll
            for (int r = 0; r < 4; r++)
                #pragma unroll
                for (int j = 0; j < 2; j++)
                    wmma::mma_sync(c[r][j], a[r], b[j], c[r][j]);
        }
    }

    cp_wait<0>();
    __syncthreads();

    float* Cs = (float*)smc;  // 128 x 132
    #pragma unroll
    for (int r = 0; r < 4; r++)
        #pragma unroll
        for (int j = 0; j < 2; j++)
            wmma::store_matrix_sync(Cs + (wm + 16 * r) * 132 + wn + 16 * j,
                                    c[r][j], 132, wmma::mem_row_major);
    __syncthreads();

    int n = tid & 127;
    long long col = n0 + n;
    for (int m2 = tid >> 7; m2 < GBM; m2 += 2) {
        int mg = m0 + m2;
        if (mg >= M) break;
        float v = Cs[m2 * 132 + n] + bias[mg];
        if (RELU) v = fmaxf(v, 0.f);
        outp[(long long)mg * Ntot + col] = __float2bfloat16(v);
    }
}

// ---------------- fused attention with HMMA qk ----------------
__device__ __forceinline__ float warpMax(float v) {
    #pragma unroll
    for (int o = 16; o > 0; o >>= 1) v = fmaxf(v, __shfl_xor_sync(0xffffffffu, v, o));
    return v;
}
__device__ __forceinline__ float warpSum(float v) {
    #pragma unroll
    for (int o = 16; o > 0; o >>= 1) v += __shfl_xor_sync(0xffffffffu, v, o);
    return v;
}

#define AT1 64       // t1 rows per block
#define KSLD 408     // ksh / Ssh leading dim (elems)
// smem: ksh bf16[96][408] | Ssh f32[64][408] | qsh bf16[64][96] | k2 f32[408] | q2 f32[64]
#define A_KSH_B   (96 * KSLD * 2)                 // 78336
#define A_SSH_B   (64 * KSLD * 4)                 // 104448
#define A_QSH_B   (64 * 96 * 2)                   // 12288
#define ATTN_SMEM (A_KSH_B + A_SSH_B + A_QSH_B + KSLD * 4 + 64 * 4)

__global__ __launch_bounds__(256) void attn_wmma(
    const __nv_bfloat16* __restrict__ qf,   // [80][51200], col = b*1600+t1
    const __nv_bfloat16* __restrict__ kf,   // [80][14336], col = b*448+t2
    const float* __restrict__ prior, const void* __restrict__ maskp,
    float* __restrict__ attn_out, float* __restrict__ logprob_out)
{
    extern __shared__ char sm[];
    __nv_bfloat16* ksh = (__nv_bfloat16*)sm;
    float* Ssh = (float*)(sm + A_KSH_B);
    __nv_bfloat16* qsh = (__nv_bfloat16*)(sm + A_KSH_B + A_SSH_B);
    float* k2sh = (float*)(sm + A_KSH_B + A_SSH_B + A_QSH_B);
    float* q2sh = k2sh + KSLD;
    __shared__ unsigned char msh[400];

    int b = blockIdx.y;
    int t1_0 = blockIdx.x * AT1;
    int tid = threadIdx.x;
    int wid = tid >> 5;
    int lane = tid & 31;

    // mask decode
    {
        unsigned int kind = g_mask_kind;
        if (kind == 0u) {
            const int* mi = (const int*)maskp;
            for (int s = tid; s < 400; s += 256) msh[s] = (mi[b * 400 + s] != 0);
        } else if (kind == 1u) {
            const float* mf = (const float*)maskp;
            for (int s = tid; s < 400; s += 256) msh[s] = (mf[b * 400 + s] != 0.f);
        } else {
            const unsigned char* mu = (const unsigned char*)maskp;
            for (int s = tid; s < 400; s += 256) msh[s] = (mu[b * 400 + s] != 0);
        }
    }

    // zero pads of ksh: (all rows, col-uint4 50) and (rows 80..95, all 51 col-uint4)
    {
        uint4 z = {0, 0, 0, 0};
        for (int idx = tid; idx < 96 + 16 * 51; idx += 256) {
            int row, c4;
            if (idx < 96) { row = idx; c4 = 50; }
            else { int j = idx - 96; row = 80 + j / 51; c4 = j % 51; }
            *(uint4*)(ksh + row * KSLD + c4 * 8) = z;
        }
    }
    // load ksh rows 0..79 (uint4 = 8 bf16)
    for (int idx = tid; idx < 80 * 50; idx += 256) {
        int row = idx / 50, c4 = idx % 50;
        *(uint4*)(ksh + row * KSLD + c4 * 8) =
            *(const uint4*)(kf + (long long)row * 14336 + b * 448 + c4 * 8);
    }
    // load qsh transposed: qsh[r][c] = q[c][t1_0+r]
    for (int idx = tid; idx < 96 * 64; idx += 256) {
        int c = idx >> 6, r = idx & 63;
        __nv_bfloat16 v = __float2bfloat16(0.f);
        if (c < 80) v = qf[(long long)c * 51200 + b * 1600 + t1_0 + r];
        qsh[r * 96 + c] = v;
    }
    __syncthreads();

    // q2 per row (4 threads/row)
    {
        int r = tid >> 2, part = tid & 3;
        float s = 0.f;
        int c0 = part * 24, c1 = min(80, c0 + 24);
        for (int c = c0; c < c1; c++) {
            float v = __bfloat162float(qsh[r * 96 + c]);
            s += v * v;
        }
        s += __shfl_xor_sync(0xffffffffu, s, 1);
        s += __shfl_xor_sync(0xffffffffu, s, 2);
        if (part == 0) q2sh[r] = s;
    }
    // k2 per t2
    for (int t2 = tid; t2 < KSLD; t2 += 256) {
        float s = 0.f;
        if (t2 < 400)
            for (int c = 0; c < 80; c++) {
                float v = __bfloat162float(ksh[c * KSLD + t2]);
                s += v * v;
            }
        k2sh[t2] = s;
    }

    // qk GEMM: S[64][400] = qsh[64][96] @ ksh[96][400]
    {
        int wr = wid >> 2;          // 2 row groups of 32 t1
        int wc = wid & 3;           // tiles wc, wc+4, ...
        wmma::fragment<wmma::accumulator, 16, 16, 16, float> acc[2][7];
        int nt = 0;
        for (int j = wc; j < 25; j += 4) nt++;
        #pragma unroll
        for (int r = 0; r < 2; r++)
            for (int j = 0; j < 7; j++) wmma::fill_fragment(acc[r][j], 0.f);

        for (int kk = 0; kk < 96; kk += 16) {
            wmma::fragment<wmma::matrix_a, 16, 16, 16, __nv_bfloat16, wmma::row_major> a[2];
            wmma::load_matrix_sync(a[0], qsh + (wr * 32) * 96 + kk, 96);
            wmma::load_matrix_sync(a[1], qsh + (wr * 32 + 16) * 96 + kk, 96);
            int ji = 0;
            for (int j = wc; j < 25; j += 4, ji++) {
                wmma::fragment<wmma::matrix_b, 16, 16, 16, __nv_bfloat16, wmma::row_major> bfrag;
                wmma::load_matrix_sync(bfrag, ksh + kk * KSLD + j * 16, KSLD);
                wmma::mma_sync(acc[0][ji], a[0], bfrag, acc[0][ji]);
                wmma::mma_sync(acc[1][ji], a[1], bfrag, acc[1][ji]);
            }
        }
        int ji = 0;
        for (int j = wc; j < 25; j += 4, ji++) {
            wmma::store_matrix_sync(Ssh + (wr * 32) * KSLD + j * 16, acc[0][ji],
                                    KSLD, wmma::mem_row_major);
            wmma::store_matrix_sync(Ssh + (wr * 32 + 16) * KSLD + j * 16, acc[1][ji],
                                    KSLD, wmma::mem_row_major);
        }
    }
    __syncthreads();

    // per-row softmax chain; warp w owns rows w*8 .. w*8+7
    for (int rr = 0; rr < 8; rr++) {
        int r = wid * 8 + rr;
        int t1 = t1_0 + r;
        float q2v = q2sh[r];
        float sc[13];
        float m = -INFINITY;
        #pragma unroll
        for (int i = 0; i < 13; i++) {
            int s = i * 32 + lane;
            sc[i] = (s < 400) ? (-TEMP * (q2v + k2sh[s] - 2.f * Ssh[r * KSLD + s]))
                              : -INFINITY;
            m = fmaxf(m, sc[i]);
        }
        m = warpMax(m);
        float sum = 0.f;
        #pragma unroll
        for (int i = 0; i < 13; i++) sum += expf(sc[i] - m);
        sum = warpSum(sum);
        float lse = m + logf(sum);

        long long base = ((long long)b * 1600 + t1) * 400;
        float xm[13];
        float m2 = -INFINITY;
        #pragma unroll
        for (int i = 0; i < 13; i++) {
            int s = i * 32 + lane;
            if (s < 400) {
                float lp = sc[i] - lse + logf(prior[base + s] + 1e-8f);
                logprob_out[base + s] = lp;
                xm[i] = msh[s] ? -INFINITY : lp;
            } else xm[i] = -INFINITY;
            m2 = fmaxf(m2, xm[i]);
        }
        m2 = warpMax(m2);
        float s2 = 0.f;
        #pragma unroll
        for (int i = 0; i < 13; i++) {
            xm[i] = (xm[i] == -INFINITY) ? 0.f : expf(xm[i] - m2);
            s2 += xm[i];
        }
        s2 = warpSum(s2);
        float inv = 1.f / s2;
        #pragma unroll
        for (int i = 0; i < 13; i++) {
            int s = i * 32 + lane;
            if (s < 400) attn_out[base + s] = xm[i] * inv;
        }
    }
}

// ---------------- launch ----------------
extern "C" void kernel_launch(void* const* d_in, const int* in_sizes, int n_in,
                              void* d_out, int out_size)
{
    const float* queries = (const float*)d_in[0];
    const float* keys    = (const float*)d_in[1];
    const void*  mask    = (const void*)d_in[2];
    const float* prior   = (const float*)d_in[3];
    const float* spk     = (const float*)d_in[4];
    const float* Wk1 = (const float*)d_in[5];
    const float* bk1 = (const float*)d_in[6];
    const float* Wk2 = (const float*)d_in[7];
    const float* bk2 = (const float*)d_in[8];
    const float* Wq1 = (const float*)d_in[9];
    const float* bq1 = (const float*)d_in[10];
    const float* Wq2 = (const float*)d_in[11];
    const float* bq2 = (const float*)d_in[12];
    const float* Wq3 = (const float*)d_in[13];
    const float* bq3 = (const float*)d_in[14];
    const float* Wks = (const float*)d_in[15];
    const float* bks = (const float*)d_in[16];
    const float* Wqs = (const float*)d_in[17];
    const float* bqs = (const float*)d_in[18];

    float* out = (float*)d_out;
    float* attn_out = out;
    float* logprob_out = out + (long long)32 * 1600 * 400;

    float* f32 = nullptr;
    __nv_bfloat16* h = nullptr;
    cudaGetSymbolAddress((void**)&f32, g_f32);
    cudaGetSymbolAddress((void**)&h, g_bf16);

    float* sbk = f32 + F_SBK;
    float* sbq = f32 + F_SBQ;

    __nv_bfloat16* Wk1b  = h + H_WK1;
    __nv_bfloat16* Wk2b  = h + H_WK2;
    __nv_bfloat16* Wq1b  = h + H_WQ1;
    __nv_bfloat16* Wq2b  = h + H_WQ2;
    __nv_bfloat16* Wq3b  = h + H_WQ3;
    __nv_bfloat16* ikey  = h + H_IKEY;
    __nv_bfloat16* k1b   = h + H_K1;
    __nv_bfloat16* iq    = h + H_IQ;
    __nv_bfloat16* q1b   = h + H_Q1;
    __nv_bfloat16* q2b   = h + H_Q2;
    __nv_bfloat16* kflat = h + H_KOUT;
    __nv_bfloat16* qflat = h + H_Q3;

    // launches 0..4; launch 5 = conv_k1 GEMM (ncu capture slot)
    detect_mask_kind<<<1, 256>>>((const unsigned int*)mask);
    spk_proj<<<dim3(32, 2), 256>>>(spk, Wks, bks, sbk, 512);
    spk_proj<<<dim3(32, 1), 256>>>(spk, Wqs, bqs, sbq, 80);
    convert_all<<<2048, 256>>>(Wk1, Wk2, Wq1, Wq2, Wq3, h);
    im2col_k<<<8192, 256>>>(keys, sbk, ikey);

    cudaFuncSetAttribute((const void*)&gemm_bf16<true>,
                         cudaFuncAttributeMaxDynamicSharedMemorySize, GEMM_SMEM);
    cudaFuncSetAttribute((const void*)&gemm_bf16<false>,
                         cudaFuncAttributeMaxDynamicSharedMemorySize, GEMM_SMEM);

    // K path: [1024 x 14336 x 1536] relu -> [80 x 14336 x 1024]
    gemm_bf16<true><<<dim3(112, 8), 256, GEMM_SMEM>>>(Wk1b, 1536, ikey, 14336LL, bk1, k1b, 1024);

    im2col_q<<<8192, 256>>>(queries, sbq, iq);

    gemm_bf16<false><<<dim3(112, 1), 256, GEMM_SMEM>>>(Wk2b, 1024, k1b, 14336LL, bk2, kflat, 80);

    // Q path
    gemm_bf16<true><<<dim3(400, 2), 256, GEMM_SMEM>>>(Wq1b, 256, iq, 51200LL, bq1, q1b, 160);
    gemm_bf16<true><<<dim3(400, 1), 256, GEMM_SMEM>>>(Wq2b, 160, q1b, 51200LL, bq2, q2b, 80);
    gemm_bf16<false><<<dim3(400, 1), 256, GEMM_SMEM>>>(Wq3b, 96, q2b, 51200LL, bq3, qflat, 80);

    // fused attention (HMMA qk + two softmaxes)
    cudaFuncSetAttribute(attn_wmma, cudaFuncAttributeMaxDynamicSharedMemorySize, ATTN_SMEM);
    attn_wmma<<<dim3(25, 32), 256, ATTN_SMEM>>>(qflat, kflat, prior, mask, attn_out, logprob_out);
}

// round 11
// speedup vs baseline: 5.8038x; 1.1377x over previous
#include <cuda_runtime.h>
#include <cuda_bf16.h>
#include <mma.h>
#include <math.h>
#include <stdint.h>

using namespace nvcuda;

#define TEMP 0.0005f

// Shapes: B=32, C_MEL=80, C_TXT=512, C_ATT=80, T1=1600, T2=400
// Convs as flat GEMMs. K path N = 32*400 = 12800; Q path N = 32*1600 = 51200.

// ---------------- fp32 scratch ----------------
#define F_SBK   0LL              // 32*512
#define F_SBQ   16384LL          // 32*80
#define F_TOTAL 18944LL
__device__ float g_f32[F_TOTAL];

// ---------------- bf16 scratch ----------------
#define H_WK1   0LL              // 1024*1536
#define H_WK2   1572864LL        // 80*1024
#define H_WQ1   1654784LL        // 160*256
#define H_WQ2   1695744LL        // 80*160
#define H_WQ3   1708544LL        // 80*96
#define H_WEND  1716224LL
#define H_IKEY  1716224LL        // 1536*12800
#define H_K1    21377024LL       // 1024*12800
#define H_IQ    34484224LL       // 256*51200
#define H_Q1    47591424LL       // 160*51200
#define H_Q2    55783424LL       // 96*51200 (rows 80..95 stay 0)
#define H_KOUT  60698624LL       // 80*12800
#define H_Q3    61722624LL       // 80*51200
#define H_TOTAL 65818624LL
__device__ __align__(16) __nv_bfloat16 g_bf16[H_TOTAL];

// mask storage kind: 0 = int32 (0/1), 1 = float32, 2 = packed bytes
__device__ unsigned int g_mask_kind;

__global__ void detect_mask_kind(const unsigned int* __restrict__ mw)
{
    __shared__ unsigned int kinds;
    if (threadIdx.x == 0) kinds = 0u;
    __syncthreads();
    unsigned int local = 0u;
    for (int i = threadIdx.x; i < 3200; i += blockDim.x) {
        unsigned int v = mw[i];
        if (v == 0u) continue;
        else if (v == 1u) local |= 1u;
        else if (v == 0x3F800000u) local |= 2u;
        else local |= 4u;
    }
    atomicOr(&kinds, local);
    __syncthreads();
    if (threadIdx.x == 0) {
        unsigned int k = kinds;
        g_mask_kind = (k & 4u) ? 2u : ((k & 2u) ? 1u : 0u);
    }
}

// ---------------- speaker projection ----------------
__global__ __launch_bounds__(256) void spk_proj(
    const float* __restrict__ spk, const float* __restrict__ Wm,
    const float* __restrict__ bb, float* __restrict__ sb, int C)
{
    int b = blockIdx.x;
    int c = blockIdx.y * 256 + threadIdx.x;
    if (c >= C) return;
    const float* sp = spk + b * 512;
    const float4* wrow = (const float4*)(Wm + c * 512);
    const float4* sp4 = (const float4*)sp;
    float s = bb[c];
    #pragma unroll 4
    for (int j = 0; j < 128; j++) {
        float4 w = wrow[j], x = sp4[j];
        s += w.x * x.x + w.y * x.y + w.z * x.z + w.w * x.w;
    }
    sb[b * C + c] = s;
}

// ---------------- all weight conversions in one kernel ----------------
__global__ void convert_all(const float* __restrict__ Wk1, const float* __restrict__ Wk2,
                            const float* __restrict__ Wq1, const float* __restrict__ Wq2,
                            const float* __restrict__ Wq3, __nv_bfloat16* __restrict__ dst)
{
    for (long long i = blockIdx.x * (long long)blockDim.x + threadIdx.x; i < H_WEND;
         i += (long long)gridDim.x * blockDim.x) {
        const float* src; long long li; int K, Kp;
        if (i < H_WK2)      { src = Wk1; li = i - H_WK1; K = 1536; Kp = 1536; }
        else if (i < H_WQ1) { src = Wk2; li = i - H_WK2; K = 1024; Kp = 1024; }
        else if (i < H_WQ2) { src = Wq1; li = i - H_WQ1; K = 240;  Kp = 256; }
        else if (i < H_WQ3) { src = Wq2; li = i - H_WQ2; K = 160;  Kp = 160; }
        else                { src = Wq3; li = i - H_WQ3; K = 80;   Kp = 96; }
        long long m = li / Kp; int k = (int)(li - m * Kp);
        dst[i] = (k < K) ? __float2bfloat16(src[m * K + k]) : __float2bfloat16(0.f);
    }
}

// ---------------- im2col (k=3, pad=1) + speaker bias ----------------
// keys: [32][512][400] -> ikey[kk][b*400+t]
__global__ void im2col_k(const float* __restrict__ x, const float* __restrict__ sb,
                         __nv_bfloat16* __restrict__ dst)
{
    const long long n = 1536LL * 12800;
    for (long long i = blockIdx.x * (long long)blockDim.x + threadIdx.x; i < n;
         i += (long long)gridDim.x * blockDim.x) {
        int col = (int)(i % 12800);
        int kk = (int)(i / 12800);
        int b = col / 400, t = col - b * 400;
        int ci = kk / 3, tap = kk - 3 * ci;
        int ts = t + tap - 1;
        float v = 0.f;
        if (ts >= 0 && ts < 400)
            v = x[((long long)b * 512 + ci) * 400 + ts] + sb[b * 512 + ci];
        dst[i] = __float2bfloat16(v);
    }
}

__global__ void im2col_q(const float* __restrict__ x, const float* __restrict__ sb,
                         __nv_bfloat16* __restrict__ dst)
{
    const long long n = 256LL * 51200;
    for (long long i = blockIdx.x * (long long)blockDim.x + threadIdx.x; i < n;
         i += (long long)gridDim.x * blockDim.x) {
        int col = (int)(i % 51200);
        int kk = (int)(i / 51200);
        int b = col / 1600, t = col - b * 1600;
        float v = 0.f;
        if (kk < 240) {
            int ci = kk / 3, tap = kk - 3 * ci;
            int ts = t + tap - 1;
            if (ts >= 0 && ts < 1600)
                v = x[((long long)b * 80 + ci) * 1600 + ts] + sb[b * 80 + ci];
        }
        dst[i] = __float2bfloat16(v);
    }
}

// ---------------- 4-stage pipelined bf16 WMMA GEMM (bf16 flat output) ----------------
#define GBM 128
#define GBN 128
#define GBK 32
#define ASTR 56
#define BSTR 152
#define ASZ (GBM * ASTR * 2)
#define BSZ (GBK * BSTR * 2)
#define STGB (ASZ + BSZ)              // 24064
#define GEMM_SMEM (4 * STGB)          // 96256 (Cs 128*132*4=67584 fits)

__device__ __forceinline__ void ldgsts16(unsigned int dst, const void* src, bool p) {
    asm volatile("cp.async.cg.shared.global [%0], [%1], 16, %2;\n"
                 :: "r"(dst), "l"(src), "r"(p ? 16 : 0));
}
__device__ __forceinline__ void cp_commit() { asm volatile("cp.async.commit_group;\n"); }
template<int N> __device__ __forceinline__ void cp_wait() {
    asm volatile("cp.async.wait_group %0;\n" :: "n"(N));
}

template<bool RELU>
__global__ __launch_bounds__(256)
void gemm_bf16(const __nv_bfloat16* __restrict__ A, int Kp,
               const __nv_bfloat16* __restrict__ Bm, long long Ntot,
               const float* __restrict__ bias, __nv_bfloat16* __restrict__ outp, int M)
{
    extern __shared__ char smc[];
    unsigned int sbase = (unsigned int)__cvta_generic_to_shared(smc);

    int tid = threadIdx.x;
    int wid = tid >> 5;
    int n0 = blockIdx.x * GBN;
    int m0 = blockIdx.y * GBM;

    int wm = (wid >> 2) * 64;
    int wn = (wid & 3) * 32;

    wmma::fragment<wmma::accumulator, 16, 16, 16, float> c[4][2];
    #pragma unroll
    for (int i = 0; i < 4; i++)
        #pragma unroll
        for (int j = 0; j < 2; j++) wmma::fill_fragment(c[i][j], 0.f);

    int nk = Kp / GBK;   // >= 3 for all our shapes

    auto load_stage = [&](int slot, int kc) {
        unsigned int sa = sbase + slot * STGB;
        #pragma unroll
        for (int it = 0; it < 2; it++) {
            int cch = tid + it * 256;
            int row = cch >> 2;
            int coff = (cch & 3) << 3;
            bool pred = (m0 + row) < M;
            int rowc = pred ? (m0 + row) : (M - 1);
            ldgsts16(sa + row * (ASTR * 2) + ((cch & 3) << 4),
                     A + (long long)rowc * Kp + kc + coff, pred);
        }
        unsigned int sb2 = sa + ASZ;
        #pragma unroll
        for (int it = 0; it < 2; it++) {
            int cch = tid + it * 256;
            int row = cch >> 4;
            int coff = (cch & 15) << 3;
            ldgsts16(sb2 + row * (BSTR * 2) + ((cch & 15) << 4),
                     Bm + (long long)(kc + row) * Ntot + n0 + coff, true);
        }
    };

    load_stage(0, 0); cp_commit();
    load_stage(1, GBK); cp_commit();
    load_stage(2, 2 * GBK); cp_commit();

    for (int i = 0; i < nk; i++) {
        cp_wait<2>();
        __syncthreads();
        int pf = i + 3;
        if (pf < nk) load_stage(pf & 3, pf * GBK);
        cp_commit();

        const __nv_bfloat16* As = (const __nv_bfloat16*)(smc + (i & 3) * STGB);
        const __nv_bfloat16* Bs = (const __nv_bfloat16*)(smc + (i & 3) * STGB + ASZ);
        #pragma unroll
        for (int kk = 0; kk < GBK; kk += 16) {
            wmma::fragment<wmma::matrix_a, 16, 16, 16, __nv_bfloat16, wmma::row_major> a[4];
            wmma::fragment<wmma::matrix_b, 16, 16, 16, __nv_bfloat16, wmma::row_major> b[2];
            #pragma unroll
            for (int r = 0; r < 4; r++)
                wmma::load_matrix_sync(a[r], As + (wm + 16 * r) * ASTR + kk, ASTR);
            #pragma unroll
            for (int j = 0; j < 2; j++)
                wmma::load_matrix_sync(b[j], Bs + kk * BSTR + wn + 16 * j, BSTR);
            #pragma unroll
            for (int r = 0; r < 4; r++)
                #pragma unroll
                for (int j = 0; j < 2; j++)
                    wmma::mma_sync(c[r][j], a[r], b[j], c[r][j]);
        }
    }

    cp_wait<0>();
    __syncthreads();

    float* Cs = (float*)smc;  // 128 x 132
    #pragma unroll
    for (int r = 0; r < 4; r++)
        #pragma unroll
        for (int j = 0; j < 2; j++)
            wmma::store_matrix_sync(Cs + (wm + 16 * r) * 132 + wn + 16 * j,
                                    c[r][j], 132, wmma::mem_row_major);
    __syncthreads();

    int n = tid & 127;
    long long col = n0 + n;
    for (int m2 = tid >> 7; m2 < GBM; m2 += 2) {
        int mg = m0 + m2;
        if (mg >= M) break;
        float v = Cs[m2 * 132 + n] + bias[mg];
        if (RELU) v = fmaxf(v, 0.f);
        outp[(long long)mg * Ntot + col] = __float2bfloat16(v);
    }
}

// ---------------- fused attention with HMMA qk (512 threads) ----------------
__device__ __forceinline__ float warpMax(float v) {
    #pragma unroll
    for (int o = 16; o > 0; o >>= 1) v = fmaxf(v, __shfl_xor_sync(0xffffffffu, v, o));
    return v;
}
__device__ __forceinline__ float warpSum(float v) {
    #pragma unroll
    for (int o = 16; o > 0; o >>= 1) v += __shfl_xor_sync(0xffffffffu, v, o);
    return v;
}

#define AT1 64       // t1 rows per block
#define KSLD 408     // ksh / Ssh leading dim (elems)
#define A_KSH_B   (96 * KSLD * 2)                 // 78336
#define A_SSH_B   (64 * KSLD * 4)                 // 104448
#define A_QSH_B   (64 * 96 * 2)                   // 12288
#define ATTN_SMEM (A_KSH_B + A_SSH_B + A_QSH_B + KSLD * 4 + 64 * 4)

__global__ __launch_bounds__(512) void attn_wmma(
    const __nv_bfloat16* __restrict__ qf,   // [80][51200], col = b*1600+t1
    const __nv_bfloat16* __restrict__ kf,   // [80][12800], col = b*400+t2
    const float* __restrict__ prior, const void* __restrict__ maskp,
    float* __restrict__ attn_out, float* __restrict__ logprob_out)
{
    extern __shared__ char sm[];
    __nv_bfloat16* ksh = (__nv_bfloat16*)sm;
    float* Ssh = (float*)(sm + A_KSH_B);
    __nv_bfloat16* qsh = (__nv_bfloat16*)(sm + A_KSH_B + A_SSH_B);
    float* k2sh = (float*)(sm + A_KSH_B + A_SSH_B + A_QSH_B);
    float* q2sh = k2sh + KSLD;
    __shared__ unsigned char msh[400];

    int b = blockIdx.y;
    int t1_0 = blockIdx.x * AT1;
    int tid = threadIdx.x;
    int wid = tid >> 5;
    int lane = tid & 31;

    // mask decode
    {
        unsigned int kind = g_mask_kind;
        if (kind == 0u) {
            const int* mi = (const int*)maskp;
            for (int s = tid; s < 400; s += 512) msh[s] = (mi[b * 400 + s] != 0);
        } else if (kind == 1u) {
            const float* mf = (const float*)maskp;
            for (int s = tid; s < 400; s += 512) msh[s] = (mf[b * 400 + s] != 0.f);
        } else {
            const unsigned char* mu = (const unsigned char*)maskp;
            for (int s = tid; s < 400; s += 512) msh[s] = (mu[b * 400 + s] != 0);
        }
    }

    // zero pads of ksh: (all 96 rows, col-uint4 50) and (rows 80..95, all 51 col-uint4)
    {
        uint4 z = {0, 0, 0, 0};
        for (int idx = tid; idx < 96 + 16 * 51; idx += 512) {
            int row, c4;
            if (idx < 96) { row = idx; c4 = 50; }
            else { int j = idx - 96; row = 80 + j / 51; c4 = j % 51; }
            *(uint4*)(ksh + row * KSLD + c4 * 8) = z;
        }
    }
    // load ksh rows 0..79 (50 uint4 = 400 bf16 per row, exactly one batch)
    for (int idx = tid; idx < 80 * 50; idx += 512) {
        int row = idx / 50, c4 = idx % 50;
        *(uint4*)(ksh + row * KSLD + c4 * 8) =
            *(const uint4*)(kf + (long long)row * 12800 + b * 400 + c4 * 8);
    }
    // load qsh transposed: qsh[r][c] = q[c][t1_0+r]
    for (int idx = tid; idx < 96 * 64; idx += 512) {
        int c = idx >> 6, r = idx & 63;
        __nv_bfloat16 v = __float2bfloat16(0.f);
        if (c < 80) v = qf[(long long)c * 51200 + b * 1600 + t1_0 + r];
        qsh[r * 96 + c] = v;
    }
    __syncthreads();

    // q2 per row (8 threads/row, 10 cols each)
    {
        int r = tid >> 3, part = tid & 7;
        float s = 0.f;
        int c0 = part * 10;
        for (int c = c0; c < c0 + 10; c++) {
            float v = __bfloat162float(qsh[r * 96 + c]);
            s += v * v;
        }
        s += __shfl_xor_sync(0xffffffffu, s, 1);
        s += __shfl_xor_sync(0xffffffffu, s, 2);
        s += __shfl_xor_sync(0xffffffffu, s, 4);
        if (part == 0) q2sh[r] = s;
    }
    // k2 per t2
    for (int t2 = tid; t2 < KSLD; t2 += 512) {
        float s = 0.f;
        if (t2 < 400)
            for (int c = 0; c < 80; c++) {
                float v = __bfloat162float(ksh[c * KSLD + t2]);
                s += v * v;
            }
        k2sh[t2] = s;
    }

    // qk GEMM: S[64][400] = qsh[64][96] @ ksh[96][400]; 16 warps: 2(m) x 8(n)
    {
        int wr = wid >> 3;          // 0/1 -> rows wr*32
        int wc = wid & 7;           // tiles wc, wc+8, wc+16, wc+24(<25)
        wmma::fragment<wmma::accumulator, 16, 16, 16, float> acc[2][4];
        #pragma unroll
        for (int r = 0; r < 2; r++)
            #pragma unroll
            for (int j = 0; j < 4; j++) wmma::fill_fragment(acc[r][j], 0.f);

        for (int kk = 0; kk < 96; kk += 16) {
            wmma::fragment<wmma::matrix_a, 16, 16, 16, __nv_bfloat16, wmma::row_major> a[2];
            wmma::load_matrix_sync(a[0], qsh + (wr * 32) * 96 + kk, 96);
            wmma::load_matrix_sync(a[1], qsh + (wr * 32 + 16) * 96 + kk, 96);
            int ji = 0;
            for (int j = wc; j < 25; j += 8, ji++) {
                wmma::fragment<wmma::matrix_b, 16, 16, 16, __nv_bfloat16, wmma::row_major> bfrag;
                wmma::load_matrix_sync(bfrag, ksh + kk * KSLD + j * 16, KSLD);
                wmma::mma_sync(acc[0][ji], a[0], bfrag, acc[0][ji]);
                wmma::mma_sync(acc[1][ji], a[1], bfrag, acc[1][ji]);
            }
        }
        int ji = 0;
        for (int j = wc; j < 25; j += 8, ji++) {
            wmma::store_matrix_sync(Ssh + (wr * 32) * KSLD + j * 16, acc[0][ji],
                                    KSLD, wmma::mem_row_major);
            wmma::store_matrix_sync(Ssh + (wr * 32 + 16) * KSLD + j * 16, acc[1][ji],
                                    KSLD, wmma::mem_row_major);
        }
    }
    __syncthreads();

    // per-row softmax chain; warp w owns rows w*4 .. w*4+3
    for (int rr = 0; rr < 4; rr++) {
        int r = wid * 4 + rr;
        int t1 = t1_0 + r;
        float q2v = q2sh[r];
        float sc[13];
        float m = -INFINITY;
        #pragma unroll
        for (int i = 0; i < 13; i++) {
            int s = i * 32 + lane;
            sc[i] = (s < 400) ? (-TEMP * (q2v + k2sh[s] - 2.f * Ssh[r * KSLD + s]))
                              : -INFINITY;
            m = fmaxf(m, sc[i]);
        }
        m = warpMax(m);
        float sum = 0.f;
        #pragma unroll
        for (int i = 0; i < 13; i++) sum += __expf(sc[i] - m);
        sum = warpSum(sum);
        float lse = m + __logf(sum);

        long long base = ((long long)b * 1600 + t1) * 400;
        float xm[13];
        float m2 = -INFINITY;
        #pragma unroll
        for (int i = 0; i < 13; i++) {
            int s = i * 32 + lane;
            if (s < 400) {
                float lp = sc[i] - lse + __logf(prior[base + s] + 1e-8f);
                logprob_out[base + s] = lp;
                xm[i] = msh[s] ? -INFINITY : lp;
            } else xm[i] = -INFINITY;
            m2 = fmaxf(m2, xm[i]);
        }
        m2 = warpMax(m2);
        float s2 = 0.f;
        #pragma unroll
        for (int i = 0; i < 13; i++) {
            xm[i] = (xm[i] == -INFINITY) ? 0.f : __expf(xm[i] - m2);
            s2 += xm[i];
        }
        s2 = warpSum(s2);
        float inv = 1.f / s2;
        #pragma unroll
        for (int i = 0; i < 13; i++) {
            int s = i * 32 + lane;
            if (s < 400) attn_out[base + s] = xm[i] * inv;
        }
    }
}

// ---------------- launch ----------------
extern "C" void kernel_launch(void* const* d_in, const int* in_sizes, int n_in,
                              void* d_out, int out_size)
{
    const float* queries = (const float*)d_in[0];
    const float* keys    = (const float*)d_in[1];
    const void*  mask    = (const void*)d_in[2];
    const float* prior   = (const float*)d_in[3];
    const float* spk     = (const float*)d_in[4];
    const float* Wk1 = (const float*)d_in[5];
    const float* bk1 = (const float*)d_in[6];
    const float* Wk2 = (const float*)d_in[7];
    const float* bk2 = (const float*)d_in[8];
    const float* Wq1 = (const float*)d_in[9];
    const float* bq1 = (const float*)d_in[10];
    const float* Wq2 = (const float*)d_in[11];
    const float* bq2 = (const float*)d_in[12];
    const float* Wq3 = (const float*)d_in[13];
    const float* bq3 = (const float*)d_in[14];
    const float* Wks = (const float*)d_in[15];
    const float* bks = (const float*)d_in[16];
    const float* Wqs = (const float*)d_in[17];
    const float* bqs = (const float*)d_in[18];

    float* out = (float*)d_out;
    float* attn_out = out;
    float* logprob_out = out + (long long)32 * 1600 * 400;

    float* f32 = nullptr;
    __nv_bfloat16* h = nullptr;
    cudaGetSymbolAddress((void**)&f32, g_f32);
    cudaGetSymbolAddress((void**)&h, g_bf16);

    float* sbk = f32 + F_SBK;
    float* sbq = f32 + F_SBQ;

    __nv_bfloat16* Wk1b  = h + H_WK1;
    __nv_bfloat16* Wk2b  = h + H_WK2;
    __nv_bfloat16* Wq1b  = h + H_WQ1;
    __nv_bfloat16* Wq2b  = h + H_WQ2;
    __nv_bfloat16* Wq3b  = h + H_WQ3;
    __nv_bfloat16* ikey  = h + H_IKEY;
    __nv_bfloat16* k1b   = h + H_K1;
    __nv_bfloat16* iq    = h + H_IQ;
    __nv_bfloat16* q1b   = h + H_Q1;
    __nv_bfloat16* q2b   = h + H_Q2;
    __nv_bfloat16* kflat = h + H_KOUT;
    __nv_bfloat16* qflat = h + H_Q3;

    cudaFuncSetAttribute((const void*)&gemm_bf16<true>,
                         cudaFuncAttributeMaxDynamicSharedMemorySize, GEMM_SMEM);
    cudaFuncSetAttribute((const void*)&gemm_bf16<false>,
                         cudaFuncAttributeMaxDynamicSharedMemorySize, GEMM_SMEM);
    cudaFuncSetAttribute(attn_wmma, cudaFuncAttributeMaxDynamicSharedMemorySize, ATTN_SMEM);

    // launch index 3 (= ncu capture slot 5 with the harness's +2 shift) is the big GEMM
    spk_proj<<<dim3(32, 2), 256>>>(spk, Wks, bks, sbk, 512);          // 0
    convert_all<<<2048, 256>>>(Wk1, Wk2, Wq1, Wq2, Wq3, h);           // 1
    im2col_k<<<8192, 256>>>(keys, sbk, ikey);                         // 2
    // K conv1: [1024 x 12800 x 1536] + relu
    gemm_bf16<true><<<dim3(100, 8), 256, GEMM_SMEM>>>(Wk1b, 1536, ikey, 12800LL, bk1, k1b, 1024); // 3

    detect_mask_kind<<<1, 256>>>((const unsigned int*)mask);          // 4
    spk_proj<<<dim3(32, 1), 256>>>(spk, Wqs, bqs, sbq, 80);           // 5
    im2col_q<<<8192, 256>>>(queries, sbq, iq);                        // 6

    // K conv2: [80 x 12800 x 1024]
    gemm_bf16<false><<<dim3(100, 1), 256, GEMM_SMEM>>>(Wk2b, 1024, k1b, 12800LL, bk2, kflat, 80);

    // Q path
    gemm_bf16<true><<<dim3(400, 2), 256, GEMM_SMEM>>>(Wq1b, 256, iq, 51200LL, bq1, q1b, 160);
    gemm_bf16<true><<<dim3(400, 1), 256, GEMM_SMEM>>>(Wq2b, 160, q1b, 51200LL, bq2, q2b, 80);
    gemm_bf16<false><<<dim3(400, 1), 256, GEMM_SMEM>>>(Wq3b, 96, q2b, 51200LL, bq3, qflat, 80);

    // fused attention (HMMA qk + two softmaxes)
    attn_wmma<<<dim3(25, 32), 512, ATTN_SMEM>>>(qflat, kflat, prior, mask, attn_out, logprob_out);
}